// round 6
// baseline (speedup 1.0000x reference)
#include <cuda_runtime.h>
#include <cuda_bf16.h>
#include <mma.h>
#include <cstdint>

using namespace nvcuda;

// ---------------- problem constants ----------------
#define BATCH      4
#define N1_PER     16384
#define N2_PER     4096
#define N1_TOT     (BATCH * N1_PER)    // 65536
#define N2_TOT     (BATCH * N2_PER)    // 16384
#define C_IN       512
#define C_OUT      256
#define BN_EPS     1e-5f

// ---------------- device scratch (static, allocation-free) ----------------
__device__ float g_h2[N2_TOT * C_OUT];                    // 16 MB
__device__ __nv_bfloat16 g_x1h[N1_TOT * C_OUT];
__device__ __nv_bfloat16 g_x1l[N1_TOT * C_OUT];
__device__ __nv_bfloat16 g_x2h[N2_TOT * C_IN];
__device__ __nv_bfloat16 g_x2l[N2_TOT * C_IN];
__device__ __nv_bfloat16 g_W1h[C_OUT * C_OUT];
__device__ __nv_bfloat16 g_W1l[C_OUT * C_OUT];
__device__ __nv_bfloat16 g_W2h[C_OUT * C_IN];
__device__ __nv_bfloat16 g_W2l[C_OUT * C_IN];
__device__ float g_c1[C_OUT];
__device__ float g_c2[C_OUT];

// -------- BN fold + bf16 split of weights: w = W[n,k]*s_n -> (hi, lo) ------
template <int WHICH>
__global__ void fold_convert_W(const float* __restrict__ W, const float* __restrict__ b,
                               const float* __restrict__ g, const float* __restrict__ be,
                               const float* __restrict__ m, const float* __restrict__ v)
{
    const int Kd = (WHICH == 0) ? C_OUT : C_IN;
    __nv_bfloat16* Wh = (WHICH == 0) ? g_W1h : g_W2h;
    __nv_bfloat16* Wl = (WHICH == 0) ? g_W1l : g_W2l;
    float* cf = (WHICH == 0) ? g_c1 : g_c2;
    int n = blockIdx.x;
    float s = g[n] / sqrtf(v[n] + BN_EPS);
    if (threadIdx.x == 0) cf[n] = (b[n] - m[n]) * s + be[n];
    for (int k = threadIdx.x; k < Kd; k += blockDim.x) {
        float w = W[n * Kd + k] * s;
        __nv_bfloat16 h = __float2bfloat16(w);
        Wh[n * Kd + k] = h;
        Wl[n * Kd + k] = __float2bfloat16(w - __bfloat162float(h));
    }
}

// -------- bf16 split of activations ---------------------------------------
__global__ void convert_x(const float* __restrict__ x,
                          __nv_bfloat16* __restrict__ xh,
                          __nv_bfloat16* __restrict__ xl, int n)
{
    int i = (blockIdx.x * blockDim.x + threadIdx.x) * 4;
    if (i >= n) return;
    float4 v = *(const float4*)(x + i);
    __nv_bfloat16 h0 = __float2bfloat16(v.x), h1 = __float2bfloat16(v.y);
    __nv_bfloat16 h2 = __float2bfloat16(v.z), h3 = __float2bfloat16(v.w);
    __nv_bfloat16 l0 = __float2bfloat16(v.x - __bfloat162float(h0));
    __nv_bfloat16 l1 = __float2bfloat16(v.y - __bfloat162float(h1));
    __nv_bfloat16 l2 = __float2bfloat16(v.z - __bfloat162float(h2));
    __nv_bfloat16 l3 = __float2bfloat16(v.w - __bfloat162float(h3));
    ushort4 ph = make_ushort4(__bfloat16_as_ushort(h0), __bfloat16_as_ushort(h1),
                              __bfloat16_as_ushort(h2), __bfloat16_as_ushort(h3));
    ushort4 pl = make_ushort4(__bfloat16_as_ushort(l0), __bfloat16_as_ushort(l1),
                              __bfloat16_as_ushort(l2), __bfloat16_as_ushort(l3));
    *(ushort4*)(xh + i) = ph;
    *(ushort4*)(xl + i) = pl;
}

// -------- tensor-core GEMM: C = relu( Ah*Bh + Ah*Bl + Al*Bh + bias ) ------
// (R4 proven version) Block tile 128x128, 8 warps (2 x 4), warp tile 64x32.
// 3 phases folded into one step counter; double-buffered smem tiles.
#define LDS_AB 40
#define LDS_C  132
#define TILE_ELEMS (128 * LDS_AB)

template <int WHICH>
__global__ __launch_bounds__(256) void gemm_wmma(float* __restrict__ Cout)
{
    constexpr int K = (WHICH == 0) ? C_OUT : C_IN;
    constexpr int KSTEPS = K / 32;
    constexpr int NSTEP = 3 * KSTEPS;

    const __nv_bfloat16* __restrict__ Ah = (WHICH == 0) ? g_x1h : g_x2h;
    const __nv_bfloat16* __restrict__ Al = (WHICH == 0) ? g_x1l : g_x2l;
    const __nv_bfloat16* __restrict__ Bh = (WHICH == 0) ? g_W1h : g_W2h;
    const __nv_bfloat16* __restrict__ Bl = (WHICH == 0) ? g_W1l : g_W2l;
    const float* __restrict__ cb = (WHICH == 0) ? g_c1 : g_c2;
    float* __restrict__ Cp = (WHICH == 0) ? Cout : g_h2;

    extern __shared__ __align__(16) char smem_raw[];
    __nv_bfloat16* As = (__nv_bfloat16*)smem_raw;          // [2][TILE_ELEMS]
    __nv_bfloat16* Bs = As + 2 * TILE_ELEMS;               // [2][TILE_ELEMS]
    float* Cs = (float*)smem_raw;                          // [128][132]

    const int tid = threadIdx.x;
    const int wid = tid >> 5;
    const int warp_m = wid >> 2;          // 0..1
    const int warp_n = wid & 3;           // 0..3
    const int bn = blockIdx.x * 128;
    const int bm = blockIdx.y * 128;

    wmma::fragment<wmma::accumulator, 16, 16, 16, float> acc[4][2];
#pragma unroll
    for (int i = 0; i < 4; i++)
#pragma unroll
        for (int j = 0; j < 2; j++) wmma::fill_fragment(acc[i][j], 0.0f);

    auto load_tile = [&](int s, int buf) {
        const int phase = s / KSTEPS;
        const int kk = (s % KSTEPS) * 32;
        const __nv_bfloat16* __restrict__ Ap = (phase == 2) ? Al : Ah;
        const __nv_bfloat16* __restrict__ Bp = (phase == 1) ? Bl : Bh;
#pragma unroll
        for (int j = 0; j < 2; j++) {
            int idx = tid + j * 256;            // 0..511
            int r = idx >> 2;
            int c8 = (idx & 3) * 8;
            uint4 va = *(const uint4*)(Ap + (size_t)(bm + r) * K + kk + c8);
            *(uint4*)(As + buf * TILE_ELEMS + r * LDS_AB + c8) = va;
            uint4 vb = *(const uint4*)(Bp + (size_t)(bn + r) * K + kk + c8);
            *(uint4*)(Bs + buf * TILE_ELEMS + r * LDS_AB + c8) = vb;
        }
    };

    load_tile(0, 0);
    __syncthreads();

    for (int s = 0; s < NSTEP; s++) {
        const int buf = s & 1;
        if (s + 1 < NSTEP) load_tile(s + 1, buf ^ 1);

        const __nv_bfloat16* Ab = As + buf * TILE_ELEMS;
        const __nv_bfloat16* Bb = Bs + buf * TILE_ELEMS;
#pragma unroll
        for (int kf = 0; kf < 2; kf++) {
            wmma::fragment<wmma::matrix_a, 16, 16, 16, __nv_bfloat16, wmma::row_major> af[4];
            wmma::fragment<wmma::matrix_b, 16, 16, 16, __nv_bfloat16, wmma::col_major> bf[2];
#pragma unroll
            for (int i = 0; i < 4; i++)
                wmma::load_matrix_sync(af[i], Ab + (warp_m * 64 + i * 16) * LDS_AB + kf * 16, LDS_AB);
#pragma unroll
            for (int j = 0; j < 2; j++)
                wmma::load_matrix_sync(bf[j], Bb + (warp_n * 32 + j * 16) * LDS_AB + kf * 16, LDS_AB);
#pragma unroll
            for (int i = 0; i < 4; i++)
#pragma unroll
                for (int j = 0; j < 2; j++)
                    wmma::mma_sync(acc[i][j], af[i], bf[j], acc[i][j]);
        }
        __syncthreads();
    }

    // epilogue: dump accum to smem (fp32), then bias + relu + vectorized store
#pragma unroll
    for (int i = 0; i < 4; i++)
#pragma unroll
        for (int j = 0; j < 2; j++)
            wmma::store_matrix_sync(Cs + (warp_m * 64 + i * 16) * LDS_C + warp_n * 32 + j * 16,
                                    acc[i][j], LDS_C, wmma::mem_row_major);
    __syncthreads();

    const int r = tid >> 1;
    const int cbase = (tid & 1) * 64;
    const float* csrow = Cs + r * LDS_C + cbase;
    float* orow = Cp + (size_t)(bm + r) * 256 + bn + cbase;
#pragma unroll
    for (int t = 0; t < 16; t++) {
        float4 v = *(const float4*)(csrow + t * 4);
        float4 bv = *(const float4*)(cb + bn + cbase + t * 4);
        v.x = fmaxf(v.x + bv.x, 0.f);
        v.y = fmaxf(v.y + bv.y, 0.f);
        v.z = fmaxf(v.z + bv.z, 0.f);
        v.w = fmaxf(v.w + bv.w, 0.f);
        *(float4*)(orow + t * 4) = v;
    }
}

#define GEMM_SMEM (128 * LDS_C * (int)sizeof(float))

// ---------------- kNN(k=3) + inverse-distance interp + add into out -------
// Exact distances (reference-identical), 2 queries per thread to amortize
// each LDS.128 across two top-3 updates. grid: (N1_PER/512, BATCH).
#define TOP3_UPD(s, kk, A0, A1, A2, I0, I1, I2)            \
    if (s < A2) {                                          \
        if (s < A1) {                                      \
            A2 = A1; I2 = I1;                              \
            if (s < A0) { A1 = A0; I1 = I0; A0 = s; I0 = kk; } \
            else        { A1 = s;  I1 = kk; }              \
        } else { A2 = s; I2 = kk; }                        \
    }

__global__ __launch_bounds__(256) void knn_interp_kernel(
    const float* __restrict__ p1, const float* __restrict__ p2,
    float* __restrict__ out)
{
    extern __shared__ float4 pts[];   // [4096]

    const int scene = blockIdx.y;
    const int tid   = threadIdx.x;

    const float* p2s = p2 + (size_t)scene * N2_PER * 3;
    for (int i = tid; i < N2_PER; i += 256) {
        pts[i] = make_float4(p2s[3 * i + 0], p2s[3 * i + 1], p2s[3 * i + 2], 0.f);
    }
    __syncthreads();

    const int qA = scene * N1_PER + blockIdx.x * 512 + tid;
    const int qB = qA + 256;
    const float qAx = p1[3 * qA + 0], qAy = p1[3 * qA + 1], qAz = p1[3 * qA + 2];
    const float qBx = p1[3 * qB + 0], qBy = p1[3 * qB + 1], qBz = p1[3 * qB + 2];

    float a0 = 3.4e38f, a1 = 3.4e38f, a2 = 3.4e38f;
    float c0 = 3.4e38f, c1 = 3.4e38f, c2 = 3.4e38f;
    int   ia0 = 0, ia1 = 0, ia2 = 0;
    int   ib0 = 0, ib1 = 0, ib2 = 0;

#pragma unroll 4
    for (int k = 0; k < N2_PER; k++) {
        float4 p = pts[k];
        float dxA = qAx - p.x, dyA = qAy - p.y, dzA = qAz - p.z;
        float dA  = fmaf(dxA, dxA, fmaf(dyA, dyA, dzA * dzA));
        float dxB = qBx - p.x, dyB = qBy - p.y, dzB = qBz - p.z;
        float dB  = fmaf(dxB, dxB, fmaf(dyB, dyB, dzB * dzB));
        TOP3_UPD(dA, k, a0, a1, a2, ia0, ia1, ia2);
        TOP3_UPD(dB, k, c0, c1, c2, ib0, ib1, ib2);
    }

    float wA0 = 1.f / (sqrtf(fmaxf(a0, 1e-12f)) + 1e-8f);
    float wA1 = 1.f / (sqrtf(fmaxf(a1, 1e-12f)) + 1e-8f);
    float wA2 = 1.f / (sqrtf(fmaxf(a2, 1e-12f)) + 1e-8f);
    float ws = wA0 + wA1 + wA2;
    wA0 /= ws; wA1 /= ws; wA2 /= ws;

    float wB0 = 1.f / (sqrtf(fmaxf(c0, 1e-12f)) + 1e-8f);
    float wB1 = 1.f / (sqrtf(fmaxf(c1, 1e-12f)) + 1e-8f);
    float wB2 = 1.f / (sqrtf(fmaxf(c2, 1e-12f)) + 1e-8f);
    float ws2 = wB0 + wB1 + wB2;
    wB0 /= ws2; wB1 /= ws2; wB2 /= ws2;

    // warp-cooperative gather with coalesced float4 row streaming
    const unsigned full = 0xffffffffu;
    const int warp = tid >> 5, lane = tid & 31;
    const int h2base = scene * N2_PER;

#pragma unroll
    for (int half = 0; half < 2; half++) {
        float w0 = half ? wB0 : wA0, w1 = half ? wB1 : wA1, w2 = half ? wB2 : wA2;
        int   j0 = half ? ib0 : ia0, j1 = half ? ib1 : ia1, j2 = half ? ib2 : ia2;
        const int qbase = scene * N1_PER + blockIdx.x * 512 + half * 256 + warp * 32;

        for (int s = 0; s < 32; s++) {
            float ww0 = __shfl_sync(full, w0, s);
            float ww1 = __shfl_sync(full, w1, s);
            float ww2 = __shfl_sync(full, w2, s);
            int   t0  = __shfl_sync(full, j0, s);
            int   t1  = __shfl_sync(full, j1, s);
            int   t2  = __shfl_sync(full, j2, s);
            const float4* r0 = (const float4*)(g_h2 + (size_t)(h2base + t0) * 256);
            const float4* r1 = (const float4*)(g_h2 + (size_t)(h2base + t1) * 256);
            const float4* r2 = (const float4*)(g_h2 + (size_t)(h2base + t2) * 256);
            float4* o = (float4*)(out + (size_t)(qbase + s) * 256);
#pragma unroll
            for (int c = 0; c < 2; c++) {
                int ci = lane + c * 32;
                float4 x = r0[ci], y = r1[ci], z = r2[ci], ov = o[ci];
                ov.x += ww0 * x.x + ww1 * y.x + ww2 * z.x;
                ov.y += ww0 * x.y + ww1 * y.y + ww2 * z.y;
                ov.z += ww0 * x.z + ww1 * y.z + ww2 * z.z;
                ov.w += ww0 * x.w + ww1 * y.w + ww2 * z.w;
                o[ci] = ov;
            }
        }
    }
}

// ---------------- launch -----------------
extern "C" void kernel_launch(void* const* d_in, const int* in_sizes, int n_in,
                              void* d_out, int out_size)
{
    const float* p1  = (const float*)d_in[0];
    const float* x1  = (const float*)d_in[1];
    const float* p2  = (const float*)d_in[2];
    const float* x2  = (const float*)d_in[3];
    const float* W1  = (const float*)d_in[4];
    const float* b1  = (const float*)d_in[5];
    const float* g1  = (const float*)d_in[6];
    const float* be1 = (const float*)d_in[7];
    const float* m1  = (const float*)d_in[8];
    const float* v1  = (const float*)d_in[9];
    const float* W2  = (const float*)d_in[10];
    const float* b2  = (const float*)d_in[11];
    const float* g2  = (const float*)d_in[12];
    const float* be2 = (const float*)d_in[13];
    const float* m2  = (const float*)d_in[14];
    const float* v2  = (const float*)d_in[15];
    float* out = (float*)d_out;

    static bool attr_set = false;
    if (!attr_set) {
        cudaFuncSetAttribute(gemm_wmma<0>, cudaFuncAttributeMaxDynamicSharedMemorySize, GEMM_SMEM);
        cudaFuncSetAttribute(gemm_wmma<1>, cudaFuncAttributeMaxDynamicSharedMemorySize, GEMM_SMEM);
        cudaFuncSetAttribute(knn_interp_kernel, cudaFuncAttributeMaxDynamicSharedMemorySize,
                             N2_PER * (int)sizeof(float4));
        attr_set = true;
    }

    // fold BN into weights + bf16 split
    fold_convert_W<0><<<C_OUT, 128>>>(W1, b1, g1, be1, m1, v1);
    fold_convert_W<1><<<C_OUT, 128>>>(W2, b2, g2, be2, m2, v2);

    // bf16 split of activations
    {
        __nv_bfloat16 *x1h, *x1l, *x2h, *x2l;
        cudaGetSymbolAddress((void**)&x1h, g_x1h);
        cudaGetSymbolAddress((void**)&x1l, g_x1l);
        cudaGetSymbolAddress((void**)&x2h, g_x2h);
        cudaGetSymbolAddress((void**)&x2l, g_x2l);
        int n1 = N1_TOT * C_OUT, n2 = N2_TOT * C_IN;
        convert_x<<<n1 / 4 / 256, 256>>>(x1, x1h, x1l, n1);
        convert_x<<<n2 / 4 / 256, 256>>>(x2, x2h, x2l, n2);
    }

    // h1 = relu(bn(x1@W1^T)) -> out
    {
        dim3 grid1(2, N1_TOT / 128);
        gemm_wmma<0><<<grid1, 256, GEMM_SMEM>>>(out);
    }
    // h2 = relu(bn(x2@W2^T)) -> g_h2
    {
        dim3 grid2(2, N2_TOT / 128);
        gemm_wmma<1><<<grid2, 256, GEMM_SMEM>>>(out);
    }

    // kNN interpolation, accumulate into out
    dim3 gridk(N1_PER / 512, BATCH);
    knn_interp_kernel<<<gridk, 256, N2_PER * sizeof(float4)>>>(p1, p2, out);
}

// round 7
// speedup vs baseline: 1.3115x; 1.3115x over previous
#include <cuda_runtime.h>
#include <cuda_bf16.h>
#include <mma.h>
#include <cstdint>

using namespace nvcuda;

// ---------------- problem constants ----------------
#define BATCH      4
#define N1_PER     16384
#define N2_PER     4096
#define N1_TOT     (BATCH * N1_PER)    // 65536
#define N2_TOT     (BATCH * N2_PER)    // 16384
#define C_IN       512
#define C_OUT      256
#define BN_EPS     1e-5f

// ---------------- device scratch (static, allocation-free) ----------------
__device__ float g_h2[N2_TOT * C_OUT];                    // 16 MB
__device__ __nv_bfloat16 g_x1h[N1_TOT * C_OUT];
__device__ __nv_bfloat16 g_x1l[N1_TOT * C_OUT];
__device__ __nv_bfloat16 g_x2h[N2_TOT * C_IN];
__device__ __nv_bfloat16 g_x2l[N2_TOT * C_IN];
__device__ __nv_bfloat16 g_W1h[C_OUT * C_OUT];
__device__ __nv_bfloat16 g_W1l[C_OUT * C_OUT];
__device__ __nv_bfloat16 g_W2h[C_OUT * C_IN];
__device__ __nv_bfloat16 g_W2l[C_OUT * C_IN];
__device__ float g_c1[C_OUT];
__device__ float g_c2[C_OUT];

// ---------------- cp.async helpers ----------------
__device__ __forceinline__ void cp_async16(uint32_t smem, const void* gptr) {
    asm volatile("cp.async.cg.shared.global [%0], [%1], 16;" :: "r"(smem), "l"(gptr));
}
__device__ __forceinline__ void cp_commit() {
    asm volatile("cp.async.commit_group;");
}
__device__ __forceinline__ void cp_wait0() {
    asm volatile("cp.async.wait_group 0;");
}

// -------- BN fold + bf16 split of weights ---------------------------------
template <int WHICH>
__global__ void fold_convert_W(const float* __restrict__ W, const float* __restrict__ b,
                               const float* __restrict__ g, const float* __restrict__ be,
                               const float* __restrict__ m, const float* __restrict__ v)
{
    const int Kd = (WHICH == 0) ? C_OUT : C_IN;
    __nv_bfloat16* Wh = (WHICH == 0) ? g_W1h : g_W2h;
    __nv_bfloat16* Wl = (WHICH == 0) ? g_W1l : g_W2l;
    float* cf = (WHICH == 0) ? g_c1 : g_c2;
    int n = blockIdx.x;
    float s = g[n] / sqrtf(v[n] + BN_EPS);
    if (threadIdx.x == 0) cf[n] = (b[n] - m[n]) * s + be[n];
    for (int k = threadIdx.x; k < Kd; k += blockDim.x) {
        float w = W[n * Kd + k] * s;
        __nv_bfloat16 h = __float2bfloat16(w);
        Wh[n * Kd + k] = h;
        Wl[n * Kd + k] = __float2bfloat16(w - __bfloat162float(h));
    }
}

// -------- bf16 split of activations (8 elements / thread) ------------------
__global__ void convert_x(const float* __restrict__ x,
                          __nv_bfloat16* __restrict__ xh,
                          __nv_bfloat16* __restrict__ xl, int n)
{
    int i = (blockIdx.x * blockDim.x + threadIdx.x) * 8;
    if (i >= n) return;
#pragma unroll
    for (int half = 0; half < 2; half++) {
        int ii = i + half * 4;
        float4 v = *(const float4*)(x + ii);
        __nv_bfloat16 h0 = __float2bfloat16(v.x), h1 = __float2bfloat16(v.y);
        __nv_bfloat16 h2 = __float2bfloat16(v.z), h3 = __float2bfloat16(v.w);
        __nv_bfloat16 l0 = __float2bfloat16(v.x - __bfloat162float(h0));
        __nv_bfloat16 l1 = __float2bfloat16(v.y - __bfloat162float(h1));
        __nv_bfloat16 l2 = __float2bfloat16(v.z - __bfloat162float(h2));
        __nv_bfloat16 l3 = __float2bfloat16(v.w - __bfloat162float(h3));
        ushort4 ph = make_ushort4(__bfloat16_as_ushort(h0), __bfloat16_as_ushort(h1),
                                  __bfloat16_as_ushort(h2), __bfloat16_as_ushort(h3));
        ushort4 pl = make_ushort4(__bfloat16_as_ushort(l0), __bfloat16_as_ushort(l1),
                                  __bfloat16_as_ushort(l2), __bfloat16_as_ushort(l3));
        *(ushort4*)(xh + ii) = ph;
        *(ushort4*)(xl + ii) = pl;
    }
}

// -------- tensor-core GEMM: C = relu( Ah*Bh + Ah*Bl + Al*Bh + bias ) ------
// (R5 fused version — proven faster) One fused K-loop: per K-32 step load
// Ah, Al, Bh, Bl tiles (cp.async, double-buffered), issue all three MMA
// combos from one fragment set. Block 128x128, 8 warps, warp tile 64x32.
#define LDS_AB 40
#define LDS_C  132
#define TILE_ELEMS (128 * LDS_AB)

template <int WHICH>
__global__ __launch_bounds__(256) void gemm_wmma(float* __restrict__ Cout)
{
    constexpr int K = (WHICH == 0) ? C_OUT : C_IN;
    constexpr int NSTEP = K / 32;

    const __nv_bfloat16* __restrict__ Ah = (WHICH == 0) ? g_x1h : g_x2h;
    const __nv_bfloat16* __restrict__ Al = (WHICH == 0) ? g_x1l : g_x2l;
    const __nv_bfloat16* __restrict__ Bh = (WHICH == 0) ? g_W1h : g_W2h;
    const __nv_bfloat16* __restrict__ Bl = (WHICH == 0) ? g_W1l : g_W2l;
    const float* __restrict__ cb = (WHICH == 0) ? g_c1 : g_c2;
    float* __restrict__ Cp = (WHICH == 0) ? Cout : g_h2;

    extern __shared__ __align__(16) char smem_raw[];
    __nv_bfloat16* tiles = (__nv_bfloat16*)smem_raw;  // [2][4][TILE_ELEMS]: Ah,Al,Bh,Bl
    float* Cs = (float*)smem_raw;                     // [128][132] (epilogue)

    const int tid = threadIdx.x;
    const int wid = tid >> 5;
    const int warp_m = wid >> 2;          // 0..1
    const int warp_n = wid & 3;           // 0..3
    const int bn = blockIdx.x * 128;
    const int bm = blockIdx.y * 128;

    wmma::fragment<wmma::accumulator, 16, 16, 16, float> acc[4][2];
#pragma unroll
    for (int i = 0; i < 4; i++)
#pragma unroll
        for (int j = 0; j < 2; j++) wmma::fill_fragment(acc[i][j], 0.0f);

    const uint32_t smem_base = (uint32_t)__cvta_generic_to_shared(tiles);

    auto load_tiles = [&](int s, int buf) {
        const int kk = s * 32;
        const uint32_t bufoff = (uint32_t)buf * 4 * TILE_ELEMS * 2;  // bytes
#pragma unroll
        for (int j = 0; j < 8; j++) {
            int idx = tid + j * 256;                 // 0..2047
            int t   = idx >> 9;                      // 0..3
            int w   = idx & 511;
            int r   = w >> 2;
            int c   = (w & 3) * 8;
            const __nv_bfloat16* src;
            if (t == 0)      src = Ah + (size_t)(bm + r) * K + kk + c;
            else if (t == 1) src = Al + (size_t)(bm + r) * K + kk + c;
            else if (t == 2) src = Bh + (size_t)(bn + r) * K + kk + c;
            else             src = Bl + (size_t)(bn + r) * K + kk + c;
            uint32_t dst = smem_base + bufoff +
                           (uint32_t)(t * TILE_ELEMS + r * LDS_AB + c) * 2;
            cp_async16(dst, src);
        }
        cp_commit();
    };

    load_tiles(0, 0);

    for (int s = 0; s < NSTEP; s++) {
        const int buf = s & 1;
        cp_wait0();
        __syncthreads();
        if (s + 1 < NSTEP) load_tiles(s + 1, buf ^ 1);

        const __nv_bfloat16* tAh = tiles + (size_t)buf * 4 * TILE_ELEMS;
        const __nv_bfloat16* tAl = tAh + TILE_ELEMS;
        const __nv_bfloat16* tBh = tAl + TILE_ELEMS;
        const __nv_bfloat16* tBl = tBh + TILE_ELEMS;

#pragma unroll
        for (int kf = 0; kf < 2; kf++) {
            wmma::fragment<wmma::matrix_a, 16, 16, 16, __nv_bfloat16, wmma::row_major> afh[4];
            wmma::fragment<wmma::matrix_b, 16, 16, 16, __nv_bfloat16, wmma::col_major> bfh[2], bfl[2];
#pragma unroll
            for (int i = 0; i < 4; i++)
                wmma::load_matrix_sync(afh[i], tAh + (warp_m * 64 + i * 16) * LDS_AB + kf * 16, LDS_AB);
#pragma unroll
            for (int j = 0; j < 2; j++) {
                wmma::load_matrix_sync(bfh[j], tBh + (warp_n * 32 + j * 16) * LDS_AB + kf * 16, LDS_AB);
                wmma::load_matrix_sync(bfl[j], tBl + (warp_n * 32 + j * 16) * LDS_AB + kf * 16, LDS_AB);
            }
#pragma unroll
            for (int i = 0; i < 4; i++)
#pragma unroll
                for (int j = 0; j < 2; j++) {
                    wmma::mma_sync(acc[i][j], afh[i], bfh[j], acc[i][j]);
                    wmma::mma_sync(acc[i][j], afh[i], bfl[j], acc[i][j]);
                }
#pragma unroll
            for (int i = 0; i < 4; i++)
                wmma::load_matrix_sync(afh[i], tAl + (warp_m * 64 + i * 16) * LDS_AB + kf * 16, LDS_AB);
#pragma unroll
            for (int i = 0; i < 4; i++)
#pragma unroll
                for (int j = 0; j < 2; j++)
                    wmma::mma_sync(acc[i][j], afh[i], bfh[j], acc[i][j]);
        }
        __syncthreads();
    }

    // epilogue: dump accum to smem (fp32), then bias + relu + vectorized store
#pragma unroll
    for (int i = 0; i < 4; i++)
#pragma unroll
        for (int j = 0; j < 2; j++)
            wmma::store_matrix_sync(Cs + (warp_m * 64 + i * 16) * LDS_C + warp_n * 32 + j * 16,
                                    acc[i][j], LDS_C, wmma::mem_row_major);
    __syncthreads();

    const int r = tid >> 1;
    const int cbase = (tid & 1) * 64;
    const float* csrow = Cs + r * LDS_C + cbase;
    float* orow = Cp + (size_t)(bm + r) * 256 + bn + cbase;
#pragma unroll
    for (int t = 0; t < 16; t++) {
        float4 v = *(const float4*)(csrow + t * 4);
        float4 bv = *(const float4*)(cb + bn + cbase + t * 4);
        v.x = fmaxf(v.x + bv.x, 0.f);
        v.y = fmaxf(v.y + bv.y, 0.f);
        v.z = fmaxf(v.z + bv.z, 0.f);
        v.w = fmaxf(v.w + bv.w, 0.f);
        *(float4*)(orow + t * 4) = v;
    }
}

#define GEMM_SMEM (8 * TILE_ELEMS * 2 > 128 * LDS_C * 4 ? 8 * TILE_ELEMS * 2 : 128 * LDS_C * 4)

// ---------------- kNN(k=3) + inverse-distance interp + add into out -------
// (R2/R4 proven 1-query version: 256 blocks -> 2 CTAs/SM co-residency)
__global__ __launch_bounds__(256) void knn_interp_kernel(
    const float* __restrict__ p1, const float* __restrict__ p2,
    float* __restrict__ out)
{
    extern __shared__ float4 pts[];   // [4096]

    const int scene = blockIdx.y;
    const int tid   = threadIdx.x;

    const float* p2s = p2 + (size_t)scene * N2_PER * 3;
    for (int i = tid; i < N2_PER; i += 256) {
        pts[i] = make_float4(p2s[3 * i + 0], p2s[3 * i + 1], p2s[3 * i + 2], 0.f);
    }
    __syncthreads();

    const int q = scene * N1_PER + blockIdx.x * 256 + tid;
    const float qx = p1[3 * q + 0];
    const float qy = p1[3 * q + 1];
    const float qz = p1[3 * q + 2];

    float b0 = 3.4e38f, b1 = 3.4e38f, b2 = 3.4e38f;
    int   i0 = 0, i1 = 0, i2 = 0;

#pragma unroll 8
    for (int k = 0; k < N2_PER; k++) {
        float4 p = pts[k];
        float dx = qx - p.x, dy = qy - p.y, dz = qz - p.z;
        float d  = fmaf(dx, dx, fmaf(dy, dy, dz * dz));
        if (d < b2) {
            if (d < b1) {
                b2 = b1; i2 = i1;
                if (d < b0) { b1 = b0; i1 = i0; b0 = d; i0 = k; }
                else        { b1 = d;  i1 = k; }
            } else { b2 = d; i2 = k; }
        }
    }

    float w0 = 1.f / (sqrtf(fmaxf(b0, 1e-12f)) + 1e-8f);
    float w1 = 1.f / (sqrtf(fmaxf(b1, 1e-12f)) + 1e-8f);
    float w2 = 1.f / (sqrtf(fmaxf(b2, 1e-12f)) + 1e-8f);
    float ws = w0 + w1 + w2;
    w0 = w0 / ws; w1 = w1 / ws; w2 = w2 / ws;

    const unsigned full = 0xffffffffu;
    const int warp = tid >> 5, lane = tid & 31;
    const int h2base = scene * N2_PER;
    const int qbase  = scene * N1_PER + blockIdx.x * 256 + warp * 32;

    for (int s = 0; s < 32; s++) {
        float ww0 = __shfl_sync(full, w0, s);
        float ww1 = __shfl_sync(full, w1, s);
        float ww2 = __shfl_sync(full, w2, s);
        int   j0  = __shfl_sync(full, i0, s);
        int   j1  = __shfl_sync(full, i1, s);
        int   j2  = __shfl_sync(full, i2, s);
        const float4* r0 = (const float4*)(g_h2 + (size_t)(h2base + j0) * 256);
        const float4* r1 = (const float4*)(g_h2 + (size_t)(h2base + j1) * 256);
        const float4* r2 = (const float4*)(g_h2 + (size_t)(h2base + j2) * 256);
        float4* o = (float4*)(out + (size_t)(qbase + s) * 256);
#pragma unroll
        for (int c = 0; c < 2; c++) {
            int ci = lane + c * 32;
            float4 a = r0[ci], b = r1[ci], cc = r2[ci], ov = o[ci];
            ov.x += ww0 * a.x + ww1 * b.x + ww2 * cc.x;
            ov.y += ww0 * a.y + ww1 * b.y + ww2 * cc.y;
            ov.z += ww0 * a.z + ww1 * b.z + ww2 * cc.z;
            ov.w += ww0 * a.w + ww1 * b.w + ww2 * cc.w;
            o[ci] = ov;
        }
    }
}

// ---------------- launch -----------------
extern "C" void kernel_launch(void* const* d_in, const int* in_sizes, int n_in,
                              void* d_out, int out_size)
{
    const float* p1  = (const float*)d_in[0];
    const float* x1  = (const float*)d_in[1];
    const float* p2  = (const float*)d_in[2];
    const float* x2  = (const float*)d_in[3];
    const float* W1  = (const float*)d_in[4];
    const float* b1  = (const float*)d_in[5];
    const float* g1  = (const float*)d_in[6];
    const float* be1 = (const float*)d_in[7];
    const float* m1  = (const float*)d_in[8];
    const float* v1  = (const float*)d_in[9];
    const float* W2  = (const float*)d_in[10];
    const float* b2  = (const float*)d_in[11];
    const float* g2  = (const float*)d_in[12];
    const float* be2 = (const float*)d_in[13];
    const float* m2  = (const float*)d_in[14];
    const float* v2  = (const float*)d_in[15];
    float* out = (float*)d_out;

    static bool attr_set = false;
    if (!attr_set) {
        cudaFuncSetAttribute(gemm_wmma<0>, cudaFuncAttributeMaxDynamicSharedMemorySize, GEMM_SMEM);
        cudaFuncSetAttribute(gemm_wmma<1>, cudaFuncAttributeMaxDynamicSharedMemorySize, GEMM_SMEM);
        cudaFuncSetAttribute(knn_interp_kernel, cudaFuncAttributeMaxDynamicSharedMemorySize,
                             N2_PER * (int)sizeof(float4));
        attr_set = true;
    }

    // fold BN into weights + bf16 split
    fold_convert_W<0><<<C_OUT, 128>>>(W1, b1, g1, be1, m1, v1);
    fold_convert_W<1><<<C_OUT, 128>>>(W2, b2, g2, be2, m2, v2);

    // bf16 split of activations
    {
        __nv_bfloat16 *x1h, *x1l, *x2h, *x2l;
        cudaGetSymbolAddress((void**)&x1h, g_x1h);
        cudaGetSymbolAddress((void**)&x1l, g_x1l);
        cudaGetSymbolAddress((void**)&x2h, g_x2h);
        cudaGetSymbolAddress((void**)&x2l, g_x2l);
        int n1 = N1_TOT * C_OUT, n2 = N2_TOT * C_IN;
        convert_x<<<n1 / 8 / 256, 256>>>(x1, x1h, x1l, n1);
        convert_x<<<n2 / 8 / 256, 256>>>(x2, x2h, x2l, n2);
    }

    // h1 = relu(bn(x1@W1^T)) -> out
    {
        dim3 grid1(2, N1_TOT / 128);
        gemm_wmma<0><<<grid1, 256, GEMM_SMEM>>>(out);
    }
    // h2 = relu(bn(x2@W2^T)) -> g_h2
    {
        dim3 grid2(2, N2_TOT / 128);
        gemm_wmma<1><<<grid2, 256, GEMM_SMEM>>>(out);
    }

    // kNN interpolation, accumulate into out
    dim3 gridk(N1_PER / 256, BATCH);
    knn_interp_kernel<<<gridk, 256, N2_PER * sizeof(float4)>>>(p1, p2, out);
}

// round 8
// speedup vs baseline: 1.5418x; 1.1756x over previous
#include <cuda_runtime.h>
#include <cuda_bf16.h>
#include <mma.h>
#include <cstdint>

using namespace nvcuda;

// ---------------- problem constants ----------------
#define BATCH      4
#define N1_PER     16384
#define N2_PER     4096
#define N1_TOT     (BATCH * N1_PER)    // 65536
#define N2_TOT     (BATCH * N2_PER)    // 16384
#define C_IN       512
#define C_OUT      256
#define BN_EPS     1e-5f

// ---------------- device scratch (static, allocation-free) ----------------
__device__ float g_h2[N2_TOT * C_OUT];                    // 16 MB
__device__ __nv_bfloat16 g_x1h[N1_TOT * C_OUT];
__device__ __nv_bfloat16 g_x1l[N1_TOT * C_OUT];
__device__ __nv_bfloat16 g_x2h[N2_TOT * C_IN];
__device__ __nv_bfloat16 g_x2l[N2_TOT * C_IN];
__device__ __nv_bfloat16 g_W1h[C_OUT * C_OUT];
__device__ __nv_bfloat16 g_W1l[C_OUT * C_OUT];
__device__ __nv_bfloat16 g_W2h[C_OUT * C_IN];
__device__ __nv_bfloat16 g_W2l[C_OUT * C_IN];
__device__ float g_c1[C_OUT];
__device__ float g_c2[C_OUT];

// ---------------- cp.async helpers ----------------
__device__ __forceinline__ void cp_async16(uint32_t smem, const void* gptr) {
    asm volatile("cp.async.cg.shared.global [%0], [%1], 16;" :: "r"(smem), "l"(gptr));
}
__device__ __forceinline__ void cp_commit() {
    asm volatile("cp.async.commit_group;");
}
__device__ __forceinline__ void cp_wait0() {
    asm volatile("cp.async.wait_group 0;");
}

// -------- BN fold + bf16 split of weights ---------------------------------
template <int WHICH>
__global__ void fold_convert_W(const float* __restrict__ W, const float* __restrict__ b,
                               const float* __restrict__ g, const float* __restrict__ be,
                               const float* __restrict__ m, const float* __restrict__ v)
{
    const int Kd = (WHICH == 0) ? C_OUT : C_IN;
    __nv_bfloat16* Wh = (WHICH == 0) ? g_W1h : g_W2h;
    __nv_bfloat16* Wl = (WHICH == 0) ? g_W1l : g_W2l;
    float* cf = (WHICH == 0) ? g_c1 : g_c2;
    int n = blockIdx.x;
    float s = g[n] / sqrtf(v[n] + BN_EPS);
    if (threadIdx.x == 0) cf[n] = (b[n] - m[n]) * s + be[n];
    for (int k = threadIdx.x; k < Kd; k += blockDim.x) {
        float w = W[n * Kd + k] * s;
        __nv_bfloat16 h = __float2bfloat16(w);
        Wh[n * Kd + k] = h;
        Wl[n * Kd + k] = __float2bfloat16(w - __bfloat162float(h));
    }
}

// -------- bf16 split of activations (4 elements / thread — proven best) ----
__global__ void convert_x(const float* __restrict__ x,
                          __nv_bfloat16* __restrict__ xh,
                          __nv_bfloat16* __restrict__ xl, int n)
{
    int i = (blockIdx.x * blockDim.x + threadIdx.x) * 4;
    if (i >= n) return;
    float4 v = *(const float4*)(x + i);
    __nv_bfloat16 h0 = __float2bfloat16(v.x), h1 = __float2bfloat16(v.y);
    __nv_bfloat16 h2 = __float2bfloat16(v.z), h3 = __float2bfloat16(v.w);
    __nv_bfloat16 l0 = __float2bfloat16(v.x - __bfloat162float(h0));
    __nv_bfloat16 l1 = __float2bfloat16(v.y - __bfloat162float(h1));
    __nv_bfloat16 l2 = __float2bfloat16(v.z - __bfloat162float(h2));
    __nv_bfloat16 l3 = __float2bfloat16(v.w - __bfloat162float(h3));
    ushort4 ph = make_ushort4(__bfloat16_as_ushort(h0), __bfloat16_as_ushort(h1),
                              __bfloat16_as_ushort(h2), __bfloat16_as_ushort(h3));
    ushort4 pl = make_ushort4(__bfloat16_as_ushort(l0), __bfloat16_as_ushort(l1),
                              __bfloat16_as_ushort(l2), __bfloat16_as_ushort(l3));
    *(ushort4*)(xh + i) = ph;
    *(ushort4*)(xl + i) = pl;
}

// -------- tensor-core GEMM: C = relu( Ah*Bh + Ah*Bl + Al*Bh + bias ) ------
// Fused K-loop (proven R5/R7), but 4 warps/CTA with 64x64 warp tiles
// (2x2 over the 128x128 block tile) -> better HMMA:LDSM ratio.
#define LDS_AB 40
#define LDS_C  132
#define TILE_ELEMS (128 * LDS_AB)

template <int WHICH>
__global__ __launch_bounds__(128) void gemm_wmma(float* __restrict__ Cout)
{
    constexpr int K = (WHICH == 0) ? C_OUT : C_IN;
    constexpr int NSTEP = K / 32;

    const __nv_bfloat16* __restrict__ Ah = (WHICH == 0) ? g_x1h : g_x2h;
    const __nv_bfloat16* __restrict__ Al = (WHICH == 0) ? g_x1l : g_x2l;
    const __nv_bfloat16* __restrict__ Bh = (WHICH == 0) ? g_W1h : g_W2h;
    const __nv_bfloat16* __restrict__ Bl = (WHICH == 0) ? g_W1l : g_W2l;
    const float* __restrict__ cb = (WHICH == 0) ? g_c1 : g_c2;
    float* __restrict__ Cp = (WHICH == 0) ? Cout : g_h2;

    extern __shared__ __align__(16) char smem_raw[];
    __nv_bfloat16* tiles = (__nv_bfloat16*)smem_raw;  // [2][4][TILE_ELEMS]: Ah,Al,Bh,Bl
    float* Cs = (float*)smem_raw;                     // [128][132] (epilogue)

    const int tid = threadIdx.x;
    const int wid = tid >> 5;
    const int warp_m = wid >> 1;          // 0..1
    const int warp_n = wid & 1;           // 0..1
    const int bn = blockIdx.x * 128;
    const int bm = blockIdx.y * 128;

    wmma::fragment<wmma::accumulator, 16, 16, 16, float> acc[4][4];
#pragma unroll
    for (int i = 0; i < 4; i++)
#pragma unroll
        for (int j = 0; j < 4; j++) wmma::fill_fragment(acc[i][j], 0.0f);

    const uint32_t smem_base = (uint32_t)__cvta_generic_to_shared(tiles);

    // per k-step: 4 tiles x 128 rows x 32 cols = 2048 16B-chunks; 16/thread
    auto load_tiles = [&](int s, int buf) {
        const int kk = s * 32;
        const uint32_t bufoff = (uint32_t)buf * 4 * TILE_ELEMS * 2;  // bytes
#pragma unroll
        for (int j = 0; j < 16; j++) {
            int idx = tid + j * 128;                 // 0..2047
            int t   = idx >> 9;                      // 0..3
            int w   = idx & 511;
            int r   = w >> 2;
            int c   = (w & 3) * 8;
            const __nv_bfloat16* src;
            if (t == 0)      src = Ah + (size_t)(bm + r) * K + kk + c;
            else if (t == 1) src = Al + (size_t)(bm + r) * K + kk + c;
            else if (t == 2) src = Bh + (size_t)(bn + r) * K + kk + c;
            else             src = Bl + (size_t)(bn + r) * K + kk + c;
            uint32_t dst = smem_base + bufoff +
                           (uint32_t)(t * TILE_ELEMS + r * LDS_AB + c) * 2;
            cp_async16(dst, src);
        }
        cp_commit();
    };

    load_tiles(0, 0);

    for (int s = 0; s < NSTEP; s++) {
        const int buf = s & 1;
        cp_wait0();
        __syncthreads();
        if (s + 1 < NSTEP) load_tiles(s + 1, buf ^ 1);

        const __nv_bfloat16* tAh = tiles + (size_t)buf * 4 * TILE_ELEMS;
        const __nv_bfloat16* tAl = tAh + TILE_ELEMS;
        const __nv_bfloat16* tBh = tAl + TILE_ELEMS;
        const __nv_bfloat16* tBl = tBh + TILE_ELEMS;

#pragma unroll
        for (int kf = 0; kf < 2; kf++) {
            wmma::fragment<wmma::matrix_a, 16, 16, 16, __nv_bfloat16, wmma::row_major> af[4];
            wmma::fragment<wmma::matrix_b, 16, 16, 16, __nv_bfloat16, wmma::col_major> bfh[4], bfl[4];
#pragma unroll
            for (int i = 0; i < 4; i++)
                wmma::load_matrix_sync(af[i], tAh + (warp_m * 64 + i * 16) * LDS_AB + kf * 16, LDS_AB);
#pragma unroll
            for (int j = 0; j < 4; j++) {
                wmma::load_matrix_sync(bfh[j], tBh + (warp_n * 64 + j * 16) * LDS_AB + kf * 16, LDS_AB);
                wmma::load_matrix_sync(bfl[j], tBl + (warp_n * 64 + j * 16) * LDS_AB + kf * 16, LDS_AB);
            }
            // Ah*Bh + Ah*Bl
#pragma unroll
            for (int i = 0; i < 4; i++)
#pragma unroll
                for (int j = 0; j < 4; j++) {
                    wmma::mma_sync(acc[i][j], af[i], bfh[j], acc[i][j]);
                    wmma::mma_sync(acc[i][j], af[i], bfl[j], acc[i][j]);
                }
            // Al*Bh (reload af with Al frags)
#pragma unroll
            for (int i = 0; i < 4; i++)
                wmma::load_matrix_sync(af[i], tAl + (warp_m * 64 + i * 16) * LDS_AB + kf * 16, LDS_AB);
#pragma unroll
            for (int i = 0; i < 4; i++)
#pragma unroll
                for (int j = 0; j < 4; j++)
                    wmma::mma_sync(acc[i][j], af[i], bfh[j], acc[i][j]);
        }
        __syncthreads();
    }

    // epilogue: dump accum to smem (fp32), then bias + relu + vectorized store
#pragma unroll
    for (int i = 0; i < 4; i++)
#pragma unroll
        for (int j = 0; j < 4; j++)
            wmma::store_matrix_sync(Cs + (warp_m * 64 + i * 16) * LDS_C + warp_n * 64 + j * 16,
                                    acc[i][j], LDS_C, wmma::mem_row_major);
    __syncthreads();

    const int r = tid;                       // 128 threads, one row each
    const float* csrow = Cs + r * LDS_C;
    float* orow = Cp + (size_t)(bm + r) * 256 + bn;
#pragma unroll
    for (int t = 0; t < 32; t++) {
        float4 v = *(const float4*)(csrow + t * 4);
        float4 bv = *(const float4*)(cb + bn + t * 4);
        v.x = fmaxf(v.x + bv.x, 0.f);
        v.y = fmaxf(v.y + bv.y, 0.f);
        v.z = fmaxf(v.z + bv.z, 0.f);
        v.w = fmaxf(v.w + bv.w, 0.f);
        *(float4*)(orow + t * 4) = v;
    }
}

#define GEMM_SMEM (8 * TILE_ELEMS * 2 > 128 * LDS_C * 4 ? 8 * TILE_ELEMS * 2 : 128 * LDS_C * 4)

// ---------------- kNN(k=3) + inverse-distance interp + add into out -------
// 1 query/thread (proven layout); 4-wide min-filter fast path in the
// selection loop: only enter the top-3 update chain when min(d0..d3) beats
// the current 3rd-best (rare). Exact distances, ascending-index tie order.
#define TOP3_UPD(s, kk, A0, A1, A2, I0, I1, I2)            \
    if (s < A2) {                                          \
        if (s < A1) {                                      \
            A2 = A1; I2 = I1;                              \
            if (s < A0) { A1 = A0; I1 = I0; A0 = s; I0 = kk; } \
            else        { A1 = s;  I1 = kk; }              \
        } else { A2 = s; I2 = kk; }                        \
    }

__global__ __launch_bounds__(256) void knn_interp_kernel(
    const float* __restrict__ p1, const float* __restrict__ p2,
    float* __restrict__ out)
{
    extern __shared__ float4 pts[];   // [4096]

    const int scene = blockIdx.y;
    const int tid   = threadIdx.x;

    const float* p2s = p2 + (size_t)scene * N2_PER * 3;
    for (int i = tid; i < N2_PER; i += 256) {
        pts[i] = make_float4(p2s[3 * i + 0], p2s[3 * i + 1], p2s[3 * i + 2], 0.f);
    }
    __syncthreads();

    const int q = scene * N1_PER + blockIdx.x * 256 + tid;
    const float qx = p1[3 * q + 0];
    const float qy = p1[3 * q + 1];
    const float qz = p1[3 * q + 2];

    float b0 = 3.4e38f, b1 = 3.4e38f, b2 = 3.4e38f;
    int   i0 = 0, i1 = 0, i2 = 0;

#pragma unroll 2
    for (int k = 0; k < N2_PER; k += 4) {
        float4 pa = pts[k + 0];
        float4 pb = pts[k + 1];
        float4 pc = pts[k + 2];
        float4 pd = pts[k + 3];
        float dxa = qx - pa.x, dya = qy - pa.y, dza = qz - pa.z;
        float da  = fmaf(dxa, dxa, fmaf(dya, dya, dza * dza));
        float dxb = qx - pb.x, dyb = qy - pb.y, dzb = qz - pb.z;
        float db  = fmaf(dxb, dxb, fmaf(dyb, dyb, dzb * dzb));
        float dxc = qx - pc.x, dyc = qy - pc.y, dzc = qz - pc.z;
        float dc  = fmaf(dxc, dxc, fmaf(dyc, dyc, dzc * dzc));
        float dxd = qx - pd.x, dyd = qy - pd.y, dzd = qz - pd.z;
        float dd  = fmaf(dxd, dxd, fmaf(dyd, dyd, dzd * dzd));
        float m = fminf(fminf(da, db), fminf(dc, dd));
        if (m < b2) {   // rare: ~21 times per query over all 1024 groups
            TOP3_UPD(da, k + 0, b0, b1, b2, i0, i1, i2);
            TOP3_UPD(db, k + 1, b0, b1, b2, i0, i1, i2);
            TOP3_UPD(dc, k + 2, b0, b1, b2, i0, i1, i2);
            TOP3_UPD(dd, k + 3, b0, b1, b2, i0, i1, i2);
        }
    }

    float w0 = 1.f / (sqrtf(fmaxf(b0, 1e-12f)) + 1e-8f);
    float w1 = 1.f / (sqrtf(fmaxf(b1, 1e-12f)) + 1e-8f);
    float w2 = 1.f / (sqrtf(fmaxf(b2, 1e-12f)) + 1e-8f);
    float ws = w0 + w1 + w2;
    w0 = w0 / ws; w1 = w1 / ws; w2 = w2 / ws;

    const unsigned full = 0xffffffffu;
    const int warp = tid >> 5, lane = tid & 31;
    const int h2base = scene * N2_PER;
    const int qbase  = scene * N1_PER + blockIdx.x * 256 + warp * 32;

    for (int s = 0; s < 32; s++) {
        float ww0 = __shfl_sync(full, w0, s);
        float ww1 = __shfl_sync(full, w1, s);
        float ww2 = __shfl_sync(full, w2, s);
        int   j0  = __shfl_sync(full, i0, s);
        int   j1  = __shfl_sync(full, i1, s);
        int   j2  = __shfl_sync(full, i2, s);
        const float4* r0 = (const float4*)(g_h2 + (size_t)(h2base + j0) * 256);
        const float4* r1 = (const float4*)(g_h2 + (size_t)(h2base + j1) * 256);
        const float4* r2 = (const float4*)(g_h2 + (size_t)(h2base + j2) * 256);
        float4* o = (float4*)(out + (size_t)(qbase + s) * 256);
#pragma unroll
        for (int c = 0; c < 2; c++) {
            int ci = lane + c * 32;
            float4 a = r0[ci], b = r1[ci], cc = r2[ci], ov = o[ci];
            ov.x += ww0 * a.x + ww1 * b.x + ww2 * cc.x;
            ov.y += ww0 * a.y + ww1 * b.y + ww2 * cc.y;
            ov.z += ww0 * a.z + ww1 * b.z + ww2 * cc.z;
            ov.w += ww0 * a.w + ww1 * b.w + ww2 * cc.w;
            o[ci] = ov;
        }
    }
}

// ---------------- launch -----------------
extern "C" void kernel_launch(void* const* d_in, const int* in_sizes, int n_in,
                              void* d_out, int out_size)
{
    const float* p1  = (const float*)d_in[0];
    const float* x1  = (const float*)d_in[1];
    const float* p2  = (const float*)d_in[2];
    const float* x2  = (const float*)d_in[3];
    const float* W1  = (const float*)d_in[4];
    const float* b1  = (const float*)d_in[5];
    const float* g1  = (const float*)d_in[6];
    const float* be1 = (const float*)d_in[7];
    const float* m1  = (const float*)d_in[8];
    const float* v1  = (const float*)d_in[9];
    const float* W2  = (const float*)d_in[10];
    const float* b2  = (const float*)d_in[11];
    const float* g2  = (const float*)d_in[12];
    const float* be2 = (const float*)d_in[13];
    const float* m2  = (const float*)d_in[14];
    const float* v2  = (const float*)d_in[15];
    float* out = (float*)d_out;

    static bool attr_set = false;
    if (!attr_set) {
        cudaFuncSetAttribute(gemm_wmma<0>, cudaFuncAttributeMaxDynamicSharedMemorySize, GEMM_SMEM);
        cudaFuncSetAttribute(gemm_wmma<1>, cudaFuncAttributeMaxDynamicSharedMemorySize, GEMM_SMEM);
        cudaFuncSetAttribute(knn_interp_kernel, cudaFuncAttributeMaxDynamicSharedMemorySize,
                             N2_PER * (int)sizeof(float4));
        attr_set = true;
    }

    // fold BN into weights + bf16 split
    fold_convert_W<0><<<C_OUT, 128>>>(W1, b1, g1, be1, m1, v1);
    fold_convert_W<1><<<C_OUT, 128>>>(W2, b2, g2, be2, m2, v2);

    // bf16 split of activations
    {
        __nv_bfloat16 *x1h, *x1l, *x2h, *x2l;
        cudaGetSymbolAddress((void**)&x1h, g_x1h);
        cudaGetSymbolAddress((void**)&x1l, g_x1l);
        cudaGetSymbolAddress((void**)&x2h, g_x2h);
        cudaGetSymbolAddress((void**)&x2l, g_x2l);
        int n1 = N1_TOT * C_OUT, n2 = N2_TOT * C_IN;
        convert_x<<<n1 / 4 / 256, 256>>>(x1, x1h, x1l, n1);
        convert_x<<<n2 / 4 / 256, 256>>>(x2, x2h, x2l, n2);
    }

    // h1 = relu(bn(x1@W1^T)) -> out
    {
        dim3 grid1(2, N1_TOT / 128);
        gemm_wmma<0><<<grid1, 128, GEMM_SMEM>>>(out);
    }
    // h2 = relu(bn(x2@W2^T)) -> g_h2
    {
        dim3 grid2(2, N2_TOT / 128);
        gemm_wmma<1><<<grid2, 128, GEMM_SMEM>>>(out);
    }

    // kNN interpolation, accumulate into out
    dim3 gridk(N1_PER / 256, BATCH);
    knn_interp_kernel<<<gridk, 256, N2_PER * sizeof(float4)>>>(p1, p2, out);
}

// round 9
// speedup vs baseline: 1.8160x; 1.1779x over previous
#include <cuda_runtime.h>
#include <cuda_bf16.h>
#include <mma.h>
#include <cstdint>

using namespace nvcuda;

// ---------------- problem constants ----------------
#define BATCH      4
#define N1_PER     16384
#define N2_PER     4096
#define N1_TOT     (BATCH * N1_PER)    // 65536
#define N2_TOT     (BATCH * N2_PER)    // 16384
#define C_IN       512
#define C_OUT      256
#define BN_EPS     1e-5f

// ---------------- device scratch (static, allocation-free) ----------------
__device__ float g_h2[N2_TOT * C_OUT];                    // 16 MB
__device__ __nv_bfloat16 g_x1h[N1_TOT * C_OUT];
__device__ __nv_bfloat16 g_x1l[N1_TOT * C_OUT];
__device__ __nv_bfloat16 g_x2h[N2_TOT * C_IN];
__device__ __nv_bfloat16 g_x2l[N2_TOT * C_IN];
__device__ __nv_bfloat16 g_W1h[C_OUT * C_OUT];
__device__ __nv_bfloat16 g_W1l[C_OUT * C_OUT];
__device__ __nv_bfloat16 g_W2h[C_OUT * C_IN];
__device__ __nv_bfloat16 g_W2l[C_OUT * C_IN];
__device__ float g_c1[C_OUT];
__device__ float g_c2[C_OUT];
// kNN scratch (SoA)
__device__ int   g_ki0[N1_TOT], g_ki1[N1_TOT], g_ki2[N1_TOT];
__device__ float g_kw0[N1_TOT], g_kw1[N1_TOT], g_kw2[N1_TOT];

// ---------------- cp.async helpers ----------------
__device__ __forceinline__ void cp_async16(uint32_t smem, const void* gptr) {
    asm volatile("cp.async.cg.shared.global [%0], [%1], 16;" :: "r"(smem), "l"(gptr));
}
__device__ __forceinline__ void cp_commit() {
    asm volatile("cp.async.commit_group;");
}
__device__ __forceinline__ void cp_wait0() {
    asm volatile("cp.async.wait_group 0;");
}

// -------- BN fold + bf16 split of weights ---------------------------------
template <int WHICH>
__global__ void fold_convert_W(const float* __restrict__ W, const float* __restrict__ b,
                               const float* __restrict__ g, const float* __restrict__ be,
                               const float* __restrict__ m, const float* __restrict__ v)
{
    const int Kd = (WHICH == 0) ? C_OUT : C_IN;
    __nv_bfloat16* Wh = (WHICH == 0) ? g_W1h : g_W2h;
    __nv_bfloat16* Wl = (WHICH == 0) ? g_W1l : g_W2l;
    float* cf = (WHICH == 0) ? g_c1 : g_c2;
    int n = blockIdx.x;
    float s = g[n] / sqrtf(v[n] + BN_EPS);
    if (threadIdx.x == 0) cf[n] = (b[n] - m[n]) * s + be[n];
    for (int k = threadIdx.x; k < Kd; k += blockDim.x) {
        float w = W[n * Kd + k] * s;
        __nv_bfloat16 h = __float2bfloat16(w);
        Wh[n * Kd + k] = h;
        Wl[n * Kd + k] = __float2bfloat16(w - __bfloat162float(h));
    }
}

// -------- bf16 split of activations (4 elements / thread — proven best) ----
__global__ void convert_x(const float* __restrict__ x,
                          __nv_bfloat16* __restrict__ xh,
                          __nv_bfloat16* __restrict__ xl, int n)
{
    int i = (blockIdx.x * blockDim.x + threadIdx.x) * 4;
    if (i >= n) return;
    float4 v = *(const float4*)(x + i);
    __nv_bfloat16 h0 = __float2bfloat16(v.x), h1 = __float2bfloat16(v.y);
    __nv_bfloat16 h2 = __float2bfloat16(v.z), h3 = __float2bfloat16(v.w);
    __nv_bfloat16 l0 = __float2bfloat16(v.x - __bfloat162float(h0));
    __nv_bfloat16 l1 = __float2bfloat16(v.y - __bfloat162float(h1));
    __nv_bfloat16 l2 = __float2bfloat16(v.z - __bfloat162float(h2));
    __nv_bfloat16 l3 = __float2bfloat16(v.w - __bfloat162float(h3));
    ushort4 ph = make_ushort4(__bfloat16_as_ushort(h0), __bfloat16_as_ushort(h1),
                              __bfloat16_as_ushort(h2), __bfloat16_as_ushort(h3));
    ushort4 pl = make_ushort4(__bfloat16_as_ushort(l0), __bfloat16_as_ushort(l1),
                              __bfloat16_as_ushort(l2), __bfloat16_as_ushort(l3));
    *(ushort4*)(xh + i) = ph;
    *(ushort4*)(xl + i) = pl;
}

// -------- tensor-core GEMM: C = relu( Ah*Bh + Ah*Bl + Al*Bh + bias ) ------
// (R8 proven: fused K-loop, 4 warps, 64x64 warp tiles, cp.async dbuf)
#define LDS_AB 40
#define LDS_C  132
#define TILE_ELEMS (128 * LDS_AB)

template <int WHICH>
__global__ __launch_bounds__(128) void gemm_wmma(float* __restrict__ Cout)
{
    constexpr int K = (WHICH == 0) ? C_OUT : C_IN;
    constexpr int NSTEP = K / 32;

    const __nv_bfloat16* __restrict__ Ah = (WHICH == 0) ? g_x1h : g_x2h;
    const __nv_bfloat16* __restrict__ Al = (WHICH == 0) ? g_x1l : g_x2l;
    const __nv_bfloat16* __restrict__ Bh = (WHICH == 0) ? g_W1h : g_W2h;
    const __nv_bfloat16* __restrict__ Bl = (WHICH == 0) ? g_W1l : g_W2l;
    const float* __restrict__ cb = (WHICH == 0) ? g_c1 : g_c2;
    float* __restrict__ Cp = (WHICH == 0) ? Cout : g_h2;

    extern __shared__ __align__(16) char smem_raw[];
    __nv_bfloat16* tiles = (__nv_bfloat16*)smem_raw;  // [2][4][TILE_ELEMS]
    float* Cs = (float*)smem_raw;                     // [128][132] (epilogue)

    const int tid = threadIdx.x;
    const int wid = tid >> 5;
    const int warp_m = wid >> 1;
    const int warp_n = wid & 1;
    const int bn = blockIdx.x * 128;
    const int bm = blockIdx.y * 128;

    wmma::fragment<wmma::accumulator, 16, 16, 16, float> acc[4][4];
#pragma unroll
    for (int i = 0; i < 4; i++)
#pragma unroll
        for (int j = 0; j < 4; j++) wmma::fill_fragment(acc[i][j], 0.0f);

    const uint32_t smem_base = (uint32_t)__cvta_generic_to_shared(tiles);

    auto load_tiles = [&](int s, int buf) {
        const int kk = s * 32;
        const uint32_t bufoff = (uint32_t)buf * 4 * TILE_ELEMS * 2;
#pragma unroll
        for (int j = 0; j < 16; j++) {
            int idx = tid + j * 128;
            int t   = idx >> 9;
            int w   = idx & 511;
            int r   = w >> 2;
            int c   = (w & 3) * 8;
            const __nv_bfloat16* src;
            if (t == 0)      src = Ah + (size_t)(bm + r) * K + kk + c;
            else if (t == 1) src = Al + (size_t)(bm + r) * K + kk + c;
            else if (t == 2) src = Bh + (size_t)(bn + r) * K + kk + c;
            else             src = Bl + (size_t)(bn + r) * K + kk + c;
            uint32_t dst = smem_base + bufoff +
                           (uint32_t)(t * TILE_ELEMS + r * LDS_AB + c) * 2;
            cp_async16(dst, src);
        }
        cp_commit();
    };

    load_tiles(0, 0);

    for (int s = 0; s < NSTEP; s++) {
        const int buf = s & 1;
        cp_wait0();
        __syncthreads();
        if (s + 1 < NSTEP) load_tiles(s + 1, buf ^ 1);

        const __nv_bfloat16* tAh = tiles + (size_t)buf * 4 * TILE_ELEMS;
        const __nv_bfloat16* tAl = tAh + TILE_ELEMS;
        const __nv_bfloat16* tBh = tAl + TILE_ELEMS;
        const __nv_bfloat16* tBl = tBh + TILE_ELEMS;

#pragma unroll
        for (int kf = 0; kf < 2; kf++) {
            wmma::fragment<wmma::matrix_a, 16, 16, 16, __nv_bfloat16, wmma::row_major> af[4];
            wmma::fragment<wmma::matrix_b, 16, 16, 16, __nv_bfloat16, wmma::col_major> bfh[4], bfl[4];
#pragma unroll
            for (int i = 0; i < 4; i++)
                wmma::load_matrix_sync(af[i], tAh + (warp_m * 64 + i * 16) * LDS_AB + kf * 16, LDS_AB);
#pragma unroll
            for (int j = 0; j < 4; j++) {
                wmma::load_matrix_sync(bfh[j], tBh + (warp_n * 64 + j * 16) * LDS_AB + kf * 16, LDS_AB);
                wmma::load_matrix_sync(bfl[j], tBl + (warp_n * 64 + j * 16) * LDS_AB + kf * 16, LDS_AB);
            }
#pragma unroll
            for (int i = 0; i < 4; i++)
#pragma unroll
                for (int j = 0; j < 4; j++) {
                    wmma::mma_sync(acc[i][j], af[i], bfh[j], acc[i][j]);
                    wmma::mma_sync(acc[i][j], af[i], bfl[j], acc[i][j]);
                }
#pragma unroll
            for (int i = 0; i < 4; i++)
                wmma::load_matrix_sync(af[i], tAl + (warp_m * 64 + i * 16) * LDS_AB + kf * 16, LDS_AB);
#pragma unroll
            for (int i = 0; i < 4; i++)
#pragma unroll
                for (int j = 0; j < 4; j++)
                    wmma::mma_sync(acc[i][j], af[i], bfh[j], acc[i][j]);
        }
        __syncthreads();
    }

#pragma unroll
    for (int i = 0; i < 4; i++)
#pragma unroll
        for (int j = 0; j < 4; j++)
            wmma::store_matrix_sync(Cs + (warp_m * 64 + i * 16) * LDS_C + warp_n * 64 + j * 16,
                                    acc[i][j], LDS_C, wmma::mem_row_major);
    __syncthreads();

    const int r = tid;
    const float* csrow = Cs + r * LDS_C;
    float* orow = Cp + (size_t)(bm + r) * 256 + bn;
#pragma unroll
    for (int t = 0; t < 32; t++) {
        float4 v = *(const float4*)(csrow + t * 4);
        float4 bv = *(const float4*)(cb + bn + t * 4);
        v.x = fmaxf(v.x + bv.x, 0.f);
        v.y = fmaxf(v.y + bv.y, 0.f);
        v.z = fmaxf(v.z + bv.z, 0.f);
        v.w = fmaxf(v.w + bv.w, 0.f);
        *(float4*)(orow + t * 4) = v;
    }
}

#define GEMM_SMEM (8 * TILE_ELEMS * 2 > 128 * LDS_C * 4 ? 8 * TILE_ELEMS * 2 : 128 * LDS_C * 4)

// ---------------- kNN select: top-3 indices + normalized weights ----------
#define TOP3_UPD(s, kk, A0, A1, A2, I0, I1, I2)            \
    if (s < A2) {                                          \
        if (s < A1) {                                      \
            A2 = A1; I2 = I1;                              \
            if (s < A0) { A1 = A0; I1 = I0; A0 = s; I0 = kk; } \
            else        { A1 = s;  I1 = kk; }              \
        } else { A2 = s; I2 = kk; }                        \
    }

__global__ __launch_bounds__(256) void knn_select_kernel(
    const float* __restrict__ p1, const float* __restrict__ p2)
{
    extern __shared__ float4 pts[];   // [4096]

    const int scene = blockIdx.y;
    const int tid   = threadIdx.x;

    const float* p2s = p2 + (size_t)scene * N2_PER * 3;
    for (int i = tid; i < N2_PER; i += 256) {
        pts[i] = make_float4(p2s[3 * i + 0], p2s[3 * i + 1], p2s[3 * i + 2], 0.f);
    }
    __syncthreads();

    const int q = scene * N1_PER + blockIdx.x * 256 + tid;
    const float qx = p1[3 * q + 0];
    const float qy = p1[3 * q + 1];
    const float qz = p1[3 * q + 2];

    float b0 = 3.4e38f, b1 = 3.4e38f, b2 = 3.4e38f;
    int   i0 = 0, i1 = 0, i2 = 0;

#pragma unroll 2
    for (int k = 0; k < N2_PER; k += 4) {
        float4 pa = pts[k + 0];
        float4 pb = pts[k + 1];
        float4 pc = pts[k + 2];
        float4 pd = pts[k + 3];
        float dxa = qx - pa.x, dya = qy - pa.y, dza = qz - pa.z;
        float da  = fmaf(dxa, dxa, fmaf(dya, dya, dza * dza));
        float dxb = qx - pb.x, dyb = qy - pb.y, dzb = qz - pb.z;
        float db  = fmaf(dxb, dxb, fmaf(dyb, dyb, dzb * dzb));
        float dxc = qx - pc.x, dyc = qy - pc.y, dzc = qz - pc.z;
        float dc  = fmaf(dxc, dxc, fmaf(dyc, dyc, dzc * dzc));
        float dxd = qx - pd.x, dyd = qy - pd.y, dzd = qz - pd.z;
        float dd  = fmaf(dxd, dxd, fmaf(dyd, dyd, dzd * dzd));
        float m = fminf(fminf(da, db), fminf(dc, dd));
        if (m < b2) {
            TOP3_UPD(da, k + 0, b0, b1, b2, i0, i1, i2);
            TOP3_UPD(db, k + 1, b0, b1, b2, i0, i1, i2);
            TOP3_UPD(dc, k + 2, b0, b1, b2, i0, i1, i2);
            TOP3_UPD(dd, k + 3, b0, b1, b2, i0, i1, i2);
        }
    }

    float w0 = 1.f / (sqrtf(fmaxf(b0, 1e-12f)) + 1e-8f);
    float w1 = 1.f / (sqrtf(fmaxf(b1, 1e-12f)) + 1e-8f);
    float w2 = 1.f / (sqrtf(fmaxf(b2, 1e-12f)) + 1e-8f);
    float ws = w0 + w1 + w2;

    g_ki0[q] = i0; g_ki1[q] = i1; g_ki2[q] = i2;
    g_kw0[q] = w0 / ws; g_kw1[q] = w1 / ws; g_kw2[q] = w2 / ws;
}

// ---------------- kNN gather: out[q] += sum_j w_j * h2[idx_j] -------------
// No smem -> high occupancy. Warp-cooperative row streaming.
__global__ __launch_bounds__(256) void knn_gather_kernel(float* __restrict__ out)
{
    const int scene = blockIdx.y;
    const int tid   = threadIdx.x;
    const int q = scene * N1_PER + blockIdx.x * 256 + tid;

    const int   i0 = g_ki0[q], i1 = g_ki1[q], i2 = g_ki2[q];
    const float w0 = g_kw0[q], w1 = g_kw1[q], w2 = g_kw2[q];

    const unsigned full = 0xffffffffu;
    const int warp = tid >> 5, lane = tid & 31;
    const int h2base = scene * N2_PER;
    const int qbase  = scene * N1_PER + blockIdx.x * 256 + warp * 32;

    for (int s = 0; s < 32; s++) {
        float ww0 = __shfl_sync(full, w0, s);
        float ww1 = __shfl_sync(full, w1, s);
        float ww2 = __shfl_sync(full, w2, s);
        int   j0  = __shfl_sync(full, i0, s);
        int   j1  = __shfl_sync(full, i1, s);
        int   j2  = __shfl_sync(full, i2, s);
        const float4* r0 = (const float4*)(g_h2 + (size_t)(h2base + j0) * 256);
        const float4* r1 = (const float4*)(g_h2 + (size_t)(h2base + j1) * 256);
        const float4* r2 = (const float4*)(g_h2 + (size_t)(h2base + j2) * 256);
        float4* o = (float4*)(out + (size_t)(qbase + s) * 256);
#pragma unroll
        for (int c = 0; c < 2; c++) {
            int ci = lane + c * 32;
            float4 a = r0[ci], b = r1[ci], cc = r2[ci], ov = o[ci];
            ov.x += ww0 * a.x + ww1 * b.x + ww2 * cc.x;
            ov.y += ww0 * a.y + ww1 * b.y + ww2 * cc.y;
            ov.z += ww0 * a.z + ww1 * b.z + ww2 * cc.z;
            ov.w += ww0 * a.w + ww1 * b.w + ww2 * cc.w;
            o[ci] = ov;
        }
    }
}

// ---------------- launch -----------------
extern "C" void kernel_launch(void* const* d_in, const int* in_sizes, int n_in,
                              void* d_out, int out_size)
{
    const float* p1  = (const float*)d_in[0];
    const float* x1  = (const float*)d_in[1];
    const float* p2  = (const float*)d_in[2];
    const float* x2  = (const float*)d_in[3];
    const float* W1  = (const float*)d_in[4];
    const float* b1  = (const float*)d_in[5];
    const float* g1  = (const float*)d_in[6];
    const float* be1 = (const float*)d_in[7];
    const float* m1  = (const float*)d_in[8];
    const float* v1  = (const float*)d_in[9];
    const float* W2  = (const float*)d_in[10];
    const float* b2  = (const float*)d_in[11];
    const float* g2  = (const float*)d_in[12];
    const float* be2 = (const float*)d_in[13];
    const float* m2  = (const float*)d_in[14];
    const float* v2  = (const float*)d_in[15];
    float* out = (float*)d_out;

    static bool init_done = false;
    static cudaStream_t s2 = nullptr;
    static cudaEvent_t evFork = nullptr, evJoin = nullptr;
    if (!init_done) {
        cudaFuncSetAttribute(gemm_wmma<0>, cudaFuncAttributeMaxDynamicSharedMemorySize, GEMM_SMEM);
        cudaFuncSetAttribute(gemm_wmma<1>, cudaFuncAttributeMaxDynamicSharedMemorySize, GEMM_SMEM);
        cudaFuncSetAttribute(knn_select_kernel, cudaFuncAttributeMaxDynamicSharedMemorySize,
                             N2_PER * (int)sizeof(float4));
        cudaStreamCreateWithFlags(&s2, cudaStreamNonBlocking);
        cudaEventCreateWithFlags(&evFork, cudaEventDisableTiming);
        cudaEventCreateWithFlags(&evJoin, cudaEventDisableTiming);
        init_done = true;
    }

    // ---- fork: kNN selection runs concurrently on side stream ----
    cudaEventRecord(evFork, 0);
    cudaStreamWaitEvent(s2, evFork, 0);
    {
        dim3 gridk(N1_PER / 256, BATCH);
        knn_select_kernel<<<gridk, 256, N2_PER * sizeof(float4), s2>>>(p1, p2);
    }
    cudaEventRecord(evJoin, s2);

    // ---- main stream: fold + convert + both GEMMs ----
    fold_convert_W<0><<<C_OUT, 128>>>(W1, b1, g1, be1, m1, v1);
    fold_convert_W<1><<<C_OUT, 128>>>(W2, b2, g2, be2, m2, v2);

    {
        __nv_bfloat16 *x1h, *x1l, *x2h, *x2l;
        cudaGetSymbolAddress((void**)&x1h, g_x1h);
        cudaGetSymbolAddress((void**)&x1l, g_x1l);
        cudaGetSymbolAddress((void**)&x2h, g_x2h);
        cudaGetSymbolAddress((void**)&x2l, g_x2l);
        int n1 = N1_TOT * C_OUT, n2 = N2_TOT * C_IN;
        convert_x<<<n1 / 4 / 256, 256>>>(x1, x1h, x1l, n1);
        convert_x<<<n2 / 4 / 256, 256>>>(x2, x2h, x2l, n2);
    }

    {
        dim3 grid1(2, N1_TOT / 128);
        gemm_wmma<0><<<grid1, 128, GEMM_SMEM>>>(out);
    }
    {
        dim3 grid2(2, N2_TOT / 128);
        gemm_wmma<1><<<grid2, 128, GEMM_SMEM>>>(out);
    }

    // ---- join: gather needs g_h2 (gemm<1>), out (gemm<0>), and select ----
    cudaStreamWaitEvent(0, evJoin, 0);
    {
        dim3 gridk(N1_PER / 256, BATCH);
        knn_gather_kernel<<<gridk, 256>>>(out);
    }
}

// round 10
// speedup vs baseline: 1.8997x; 1.0461x over previous
#include <cuda_runtime.h>
#include <cuda_bf16.h>
#include <mma.h>
#include <cstdint>

using namespace nvcuda;

// ---------------- problem constants ----------------
#define BATCH      4
#define N1_PER     16384
#define N2_PER     4096
#define N1_TOT     (BATCH * N1_PER)    // 65536
#define N2_TOT     (BATCH * N2_PER)    // 16384
#define C_IN       512
#define C_OUT      256
#define BN_EPS     1e-5f

// ---------------- device scratch (static, allocation-free) ----------------
__device__ float g_h2[N2_TOT * C_OUT];                    // 16 MB
__device__ __nv_bfloat16 g_x1h[N1_TOT * C_OUT];
__device__ __nv_bfloat16 g_x1l[N1_TOT * C_OUT];
__device__ __nv_bfloat16 g_x2h[N2_TOT * C_IN];
__device__ __nv_bfloat16 g_x2l[N2_TOT * C_IN];
__device__ __nv_bfloat16 g_W1h[C_OUT * C_OUT];
__device__ __nv_bfloat16 g_W1l[C_OUT * C_OUT];
__device__ __nv_bfloat16 g_W2h[C_OUT * C_IN];
__device__ __nv_bfloat16 g_W2l[C_OUT * C_IN];
__device__ float g_c1[C_OUT];
__device__ float g_c2[C_OUT];
// kNN scratch (SoA)
__device__ int   g_ki0[N1_TOT], g_ki1[N1_TOT], g_ki2[N1_TOT];
__device__ float g_kw0[N1_TOT], g_kw1[N1_TOT], g_kw2[N1_TOT];

// ---------------- cp.async helpers ----------------
__device__ __forceinline__ void cp_async16(uint32_t smem, const void* gptr) {
    asm volatile("cp.async.cg.shared.global [%0], [%1], 16;" :: "r"(smem), "l"(gptr));
}
__device__ __forceinline__ void cp_commit() {
    asm volatile("cp.async.commit_group;");
}
__device__ __forceinline__ void cp_wait0() {
    asm volatile("cp.async.wait_group 0;");
}

// -------- BN fold + bf16 split of weights ---------------------------------
template <int WHICH>
__global__ void fold_convert_W(const float* __restrict__ W, const float* __restrict__ b,
                               const float* __restrict__ g, const float* __restrict__ be,
                               const float* __restrict__ m, const float* __restrict__ v)
{
    const int Kd = (WHICH == 0) ? C_OUT : C_IN;
    __nv_bfloat16* Wh = (WHICH == 0) ? g_W1h : g_W2h;
    __nv_bfloat16* Wl = (WHICH == 0) ? g_W1l : g_W2l;
    float* cf = (WHICH == 0) ? g_c1 : g_c2;
    int n = blockIdx.x;
    float s = g[n] / sqrtf(v[n] + BN_EPS);
    if (threadIdx.x == 0) cf[n] = (b[n] - m[n]) * s + be[n];
    for (int k = threadIdx.x; k < Kd; k += blockDim.x) {
        float w = W[n * Kd + k] * s;
        __nv_bfloat16 h = __float2bfloat16(w);
        Wh[n * Kd + k] = h;
        Wl[n * Kd + k] = __float2bfloat16(w - __bfloat162float(h));
    }
}

// -------- bf16 split of activations (4 elements / thread — proven best) ----
__global__ void convert_x(const float* __restrict__ x,
                          __nv_bfloat16* __restrict__ xh,
                          __nv_bfloat16* __restrict__ xl, int n)
{
    int i = (blockIdx.x * blockDim.x + threadIdx.x) * 4;
    if (i >= n) return;
    float4 v = *(const float4*)(x + i);
    __nv_bfloat16 h0 = __float2bfloat16(v.x), h1 = __float2bfloat16(v.y);
    __nv_bfloat16 h2 = __float2bfloat16(v.z), h3 = __float2bfloat16(v.w);
    __nv_bfloat16 l0 = __float2bfloat16(v.x - __bfloat162float(h0));
    __nv_bfloat16 l1 = __float2bfloat16(v.y - __bfloat162float(h1));
    __nv_bfloat16 l2 = __float2bfloat16(v.z - __bfloat162float(h2));
    __nv_bfloat16 l3 = __float2bfloat16(v.w - __bfloat162float(h3));
    ushort4 ph = make_ushort4(__bfloat16_as_ushort(h0), __bfloat16_as_ushort(h1),
                              __bfloat16_as_ushort(h2), __bfloat16_as_ushort(h3));
    ushort4 pl = make_ushort4(__bfloat16_as_ushort(l0), __bfloat16_as_ushort(l1),
                              __bfloat16_as_ushort(l2), __bfloat16_as_ushort(l3));
    *(ushort4*)(xh + i) = ph;
    *(ushort4*)(xl + i) = pl;
}

// -------- tensor-core GEMM: C = relu( Ah*Bh + Ah*Bl + Al*Bh + bias ) ------
// (R8 proven core) For WHICH==0 the epilogue additionally fuses the kNN
// gather: out = relu(gemm + bias) + w0*h2[j0] + w1*h2[j1] + w2*h2[j2].
#define LDS_AB 40
#define LDS_C  132
#define TILE_ELEMS (128 * LDS_AB)

template <int WHICH>
__global__ __launch_bounds__(128) void gemm_wmma(float* __restrict__ Cout)
{
    constexpr int K = (WHICH == 0) ? C_OUT : C_IN;
    constexpr int NSTEP = K / 32;

    const __nv_bfloat16* __restrict__ Ah = (WHICH == 0) ? g_x1h : g_x2h;
    const __nv_bfloat16* __restrict__ Al = (WHICH == 0) ? g_x1l : g_x2l;
    const __nv_bfloat16* __restrict__ Bh = (WHICH == 0) ? g_W1h : g_W2h;
    const __nv_bfloat16* __restrict__ Bl = (WHICH == 0) ? g_W1l : g_W2l;
    const float* __restrict__ cb = (WHICH == 0) ? g_c1 : g_c2;
    float* __restrict__ Cp = (WHICH == 0) ? Cout : g_h2;

    extern __shared__ __align__(16) char smem_raw[];
    __nv_bfloat16* tiles = (__nv_bfloat16*)smem_raw;  // [2][4][TILE_ELEMS]
    float* Cs = (float*)smem_raw;                     // [128][132] (epilogue)

    const int tid = threadIdx.x;
    const int wid = tid >> 5;
    const int warp_m = wid >> 1;
    const int warp_n = wid & 1;
    const int bn = blockIdx.x * 128;
    const int bm = blockIdx.y * 128;

    wmma::fragment<wmma::accumulator, 16, 16, 16, float> acc[4][4];
#pragma unroll
    for (int i = 0; i < 4; i++)
#pragma unroll
        for (int j = 0; j < 4; j++) wmma::fill_fragment(acc[i][j], 0.0f);

    const uint32_t smem_base = (uint32_t)__cvta_generic_to_shared(tiles);

    auto load_tiles = [&](int s, int buf) {
        const int kk = s * 32;
        const uint32_t bufoff = (uint32_t)buf * 4 * TILE_ELEMS * 2;
#pragma unroll
        for (int j = 0; j < 16; j++) {
            int idx = tid + j * 128;
            int t   = idx >> 9;
            int w   = idx & 511;
            int r   = w >> 2;
            int c   = (w & 3) * 8;
            const __nv_bfloat16* src;
            if (t == 0)      src = Ah + (size_t)(bm + r) * K + kk + c;
            else if (t == 1) src = Al + (size_t)(bm + r) * K + kk + c;
            else if (t == 2) src = Bh + (size_t)(bn + r) * K + kk + c;
            else             src = Bl + (size_t)(bn + r) * K + kk + c;
            uint32_t dst = smem_base + bufoff +
                           (uint32_t)(t * TILE_ELEMS + r * LDS_AB + c) * 2;
            cp_async16(dst, src);
        }
        cp_commit();
    };

    load_tiles(0, 0);

    for (int s = 0; s < NSTEP; s++) {
        const int buf = s & 1;
        cp_wait0();
        __syncthreads();
        if (s + 1 < NSTEP) load_tiles(s + 1, buf ^ 1);

        const __nv_bfloat16* tAh = tiles + (size_t)buf * 4 * TILE_ELEMS;
        const __nv_bfloat16* tAl = tAh + TILE_ELEMS;
        const __nv_bfloat16* tBh = tAl + TILE_ELEMS;
        const __nv_bfloat16* tBl = tBh + TILE_ELEMS;

#pragma unroll
        for (int kf = 0; kf < 2; kf++) {
            wmma::fragment<wmma::matrix_a, 16, 16, 16, __nv_bfloat16, wmma::row_major> af[4];
            wmma::fragment<wmma::matrix_b, 16, 16, 16, __nv_bfloat16, wmma::col_major> bfh[4], bfl[4];
#pragma unroll
            for (int i = 0; i < 4; i++)
                wmma::load_matrix_sync(af[i], tAh + (warp_m * 64 + i * 16) * LDS_AB + kf * 16, LDS_AB);
#pragma unroll
            for (int j = 0; j < 4; j++) {
                wmma::load_matrix_sync(bfh[j], tBh + (warp_n * 64 + j * 16) * LDS_AB + kf * 16, LDS_AB);
                wmma::load_matrix_sync(bfl[j], tBl + (warp_n * 64 + j * 16) * LDS_AB + kf * 16, LDS_AB);
            }
#pragma unroll
            for (int i = 0; i < 4; i++)
#pragma unroll
                for (int j = 0; j < 4; j++) {
                    wmma::mma_sync(acc[i][j], af[i], bfh[j], acc[i][j]);
                    wmma::mma_sync(acc[i][j], af[i], bfl[j], acc[i][j]);
                }
#pragma unroll
            for (int i = 0; i < 4; i++)
                wmma::load_matrix_sync(af[i], tAl + (warp_m * 64 + i * 16) * LDS_AB + kf * 16, LDS_AB);
#pragma unroll
            for (int i = 0; i < 4; i++)
#pragma unroll
                for (int j = 0; j < 4; j++)
                    wmma::mma_sync(acc[i][j], af[i], bfh[j], acc[i][j]);
        }
        __syncthreads();
    }

#pragma unroll
    for (int i = 0; i < 4; i++)
#pragma unroll
        for (int j = 0; j < 4; j++)
            wmma::store_matrix_sync(Cs + (warp_m * 64 + i * 16) * LDS_C + warp_n * 64 + j * 16,
                                    acc[i][j], LDS_C, wmma::mem_row_major);
    __syncthreads();

    if constexpr (WHICH == 0) {
        // fused epilogue: relu(gemm+bias) + kNN-weighted h2 rows -> out
        const unsigned full = 0xffffffffu;
        const int warp = tid >> 5, lane = tid & 31;
        const int scene = bm / N1_PER;              // constant per CTA
        const int h2base = scene * N2_PER;
        const int q = bm + tid;                     // this thread's query
        const int i0 = g_ki0[q], i1 = g_ki1[q], i2 = g_ki2[q];
        const float w0 = g_kw0[q], w1 = g_kw1[q], w2 = g_kw2[q];
        const float4 bv = *(const float4*)(cb + bn + lane * 4);

        for (int s = 0; s < 32; s++) {
            float ww0 = __shfl_sync(full, w0, s);
            float ww1 = __shfl_sync(full, w1, s);
            float ww2 = __shfl_sync(full, w2, s);
            int   j0  = __shfl_sync(full, i0, s);
            int   j1  = __shfl_sync(full, i1, s);
            int   j2  = __shfl_sync(full, i2, s);
            const int row = warp * 32 + s;
            const float4 a = ((const float4*)(g_h2 + (size_t)(h2base + j0) * 256 + bn))[lane];
            const float4 b = ((const float4*)(g_h2 + (size_t)(h2base + j1) * 256 + bn))[lane];
            const float4 c = ((const float4*)(g_h2 + (size_t)(h2base + j2) * 256 + bn))[lane];
            const float4 cs4 = *(const float4*)(Cs + row * LDS_C + lane * 4);
            float4 v;
            v.x = fmaxf(cs4.x + bv.x, 0.f) + ww0 * a.x + ww1 * b.x + ww2 * c.x;
            v.y = fmaxf(cs4.y + bv.y, 0.f) + ww0 * a.y + ww1 * b.y + ww2 * c.y;
            v.z = fmaxf(cs4.z + bv.z, 0.f) + ww0 * a.z + ww1 * b.z + ww2 * c.z;
            v.w = fmaxf(cs4.w + bv.w, 0.f) + ww0 * a.w + ww1 * b.w + ww2 * c.w;
            *(float4*)(Cp + (size_t)(bm + row) * 256 + bn + lane * 4) = v;
        }
    } else {
        const int r = tid;
        const float* csrow = Cs + r * LDS_C;
        float* orow = Cp + (size_t)(bm + r) * 256 + bn;
#pragma unroll
        for (int t = 0; t < 32; t++) {
            float4 v = *(const float4*)(csrow + t * 4);
            float4 bv = *(const float4*)(cb + bn + t * 4);
            v.x = fmaxf(v.x + bv.x, 0.f);
            v.y = fmaxf(v.y + bv.y, 0.f);
            v.z = fmaxf(v.z + bv.z, 0.f);
            v.w = fmaxf(v.w + bv.w, 0.f);
            *(float4*)(orow + t * 4) = v;
        }
    }
}

#define GEMM_SMEM (8 * TILE_ELEMS * 2 > 128 * LDS_C * 4 ? 8 * TILE_ELEMS * 2 : 128 * LDS_C * 4)

// ---------------- kNN select: top-3 indices + normalized weights ----------
#define TOP3_UPD(s, kk, A0, A1, A2, I0, I1, I2)            \
    if (s < A2) {                                          \
        if (s < A1) {                                      \
            A2 = A1; I2 = I1;                              \
            if (s < A0) { A1 = A0; I1 = I0; A0 = s; I0 = kk; } \
            else        { A1 = s;  I1 = kk; }              \
        } else { A2 = s; I2 = kk; }                        \
    }

__global__ __launch_bounds__(256) void knn_select_kernel(
    const float* __restrict__ p1, const float* __restrict__ p2)
{
    extern __shared__ float4 pts[];   // [4096]

    const int scene = blockIdx.y;
    const int tid   = threadIdx.x;

    const float* p2s = p2 + (size_t)scene * N2_PER * 3;
    for (int i = tid; i < N2_PER; i += 256) {
        pts[i] = make_float4(p2s[3 * i + 0], p2s[3 * i + 1], p2s[3 * i + 2], 0.f);
    }
    __syncthreads();

    const int q = scene * N1_PER + blockIdx.x * 256 + tid;
    const float qx = p1[3 * q + 0];
    const float qy = p1[3 * q + 1];
    const float qz = p1[3 * q + 2];

    float b0 = 3.4e38f, b1 = 3.4e38f, b2 = 3.4e38f;
    int   i0 = 0, i1 = 0, i2 = 0;

#pragma unroll 2
    for (int k = 0; k < N2_PER; k += 4) {
        float4 pa = pts[k + 0];
        float4 pb = pts[k + 1];
        float4 pc = pts[k + 2];
        float4 pd = pts[k + 3];
        float dxa = qx - pa.x, dya = qy - pa.y, dza = qz - pa.z;
        float da  = fmaf(dxa, dxa, fmaf(dya, dya, dza * dza));
        float dxb = qx - pb.x, dyb = qy - pb.y, dzb = qz - pb.z;
        float db  = fmaf(dxb, dxb, fmaf(dyb, dyb, dzb * dzb));
        float dxc = qx - pc.x, dyc = qy - pc.y, dzc = qz - pc.z;
        float dc  = fmaf(dxc, dxc, fmaf(dyc, dyc, dzc * dzc));
        float dxd = qx - pd.x, dyd = qy - pd.y, dzd = qz - pd.z;
        float dd  = fmaf(dxd, dxd, fmaf(dyd, dyd, dzd * dzd));
        float m = fminf(fminf(da, db), fminf(dc, dd));
        if (m < b2) {
            TOP3_UPD(da, k + 0, b0, b1, b2, i0, i1, i2);
            TOP3_UPD(db, k + 1, b0, b1, b2, i0, i1, i2);
            TOP3_UPD(dc, k + 2, b0, b1, b2, i0, i1, i2);
            TOP3_UPD(dd, k + 3, b0, b1, b2, i0, i1, i2);
        }
    }

    float w0 = 1.f / (sqrtf(fmaxf(b0, 1e-12f)) + 1e-8f);
    float w1 = 1.f / (sqrtf(fmaxf(b1, 1e-12f)) + 1e-8f);
    float w2 = 1.f / (sqrtf(fmaxf(b2, 1e-12f)) + 1e-8f);
    float ws = w0 + w1 + w2;

    g_ki0[q] = i0; g_ki1[q] = i1; g_ki2[q] = i2;
    g_kw0[q] = w0 / ws; g_kw1[q] = w1 / ws; g_kw2[q] = w2 / ws;
}

// ---------------- launch -----------------
extern "C" void kernel_launch(void* const* d_in, const int* in_sizes, int n_in,
                              void* d_out, int out_size)
{
    const float* p1  = (const float*)d_in[0];
    const float* x1  = (const float*)d_in[1];
    const float* p2  = (const float*)d_in[2];
    const float* x2  = (const float*)d_in[3];
    const float* W1  = (const float*)d_in[4];
    const float* b1  = (const float*)d_in[5];
    const float* g1  = (const float*)d_in[6];
    const float* be1 = (const float*)d_in[7];
    const float* m1  = (const float*)d_in[8];
    const float* v1  = (const float*)d_in[9];
    const float* W2  = (const float*)d_in[10];
    const float* b2  = (const float*)d_in[11];
    const float* g2  = (const float*)d_in[12];
    const float* be2 = (const float*)d_in[13];
    const float* m2  = (const float*)d_in[14];
    const float* v2  = (const float*)d_in[15];
    float* out = (float*)d_out;

    static bool init_done = false;
    static cudaStream_t s2 = nullptr;
    static cudaEvent_t evFork = nullptr, evJoin = nullptr;
    if (!init_done) {
        cudaFuncSetAttribute(gemm_wmma<0>, cudaFuncAttributeMaxDynamicSharedMemorySize, GEMM_SMEM);
        cudaFuncSetAttribute(gemm_wmma<1>, cudaFuncAttributeMaxDynamicSharedMemorySize, GEMM_SMEM);
        cudaFuncSetAttribute(knn_select_kernel, cudaFuncAttributeMaxDynamicSharedMemorySize,
                             N2_PER * (int)sizeof(float4));
        cudaStreamCreateWithFlags(&s2, cudaStreamNonBlocking);
        cudaEventCreateWithFlags(&evFork, cudaEventDisableTiming);
        cudaEventCreateWithFlags(&evJoin, cudaEventDisableTiming);
        init_done = true;
    }

    // ---- fork: kNN selection runs concurrently on side stream ----
    cudaEventRecord(evFork, 0);
    cudaStreamWaitEvent(s2, evFork, 0);
    {
        dim3 gridk(N1_PER / 256, BATCH);
        knn_select_kernel<<<gridk, 256, N2_PER * sizeof(float4), s2>>>(p1, p2);
    }
    cudaEventRecord(evJoin, s2);

    // ---- main stream: fold + convert + gemm<1> (h2) ----
    fold_convert_W<0><<<C_OUT, 128>>>(W1, b1, g1, be1, m1, v1);
    fold_convert_W<1><<<C_OUT, 128>>>(W2, b2, g2, be2, m2, v2);

    {
        __nv_bfloat16 *x1h, *x1l, *x2h, *x2l;
        cudaGetSymbolAddress((void**)&x1h, g_x1h);
        cudaGetSymbolAddress((void**)&x1l, g_x1l);
        cudaGetSymbolAddress((void**)&x2h, g_x2h);
        cudaGetSymbolAddress((void**)&x2l, g_x2l);
        int n1 = N1_TOT * C_OUT, n2 = N2_TOT * C_IN;
        convert_x<<<n2 / 4 / 256, 256>>>(x2, x2h, x2l, n2);
        convert_x<<<n1 / 4 / 256, 256>>>(x1, x1h, x1l, n1);
    }

    // h2 = relu(bn(x2@W2^T)) -> g_h2
    {
        dim3 grid2(2, N2_TOT / 128);
        gemm_wmma<1><<<grid2, 128, GEMM_SMEM>>>(out);
    }

    // ---- join: gemm<0> fused epilogue needs select results + g_h2 ----
    cudaStreamWaitEvent(0, evJoin, 0);

    // out = relu(bn(x1@W1^T)) + kNN-interp(h2)  (fused)
    {
        dim3 grid1(2, N1_TOT / 128);
        gemm_wmma<0><<<grid1, 128, GEMM_SMEM>>>(out);
    }
}

// round 11
// speedup vs baseline: 2.0171x; 1.0618x over previous
#include <cuda_runtime.h>
#include <cuda_bf16.h>
#include <mma.h>
#include <cstdint>

using namespace nvcuda;

// ---------------- problem constants ----------------
#define BATCH      4
#define N1_PER     16384
#define N2_PER     4096
#define N1_TOT     (BATCH * N1_PER)    // 65536
#define N2_TOT     (BATCH * N2_PER)    // 16384
#define C_IN       512
#define C_OUT      256
#define BN_EPS     1e-5f

// ---------------- device scratch (static, allocation-free) ----------------
__device__ float g_h2[N2_TOT * C_OUT];                    // 16 MB
__device__ __nv_bfloat16 g_x1h[N1_TOT * C_OUT];
__device__ __nv_bfloat16 g_x1l[N1_TOT * C_OUT];
__device__ __nv_bfloat16 g_x2h[N2_TOT * C_IN];
__device__ __nv_bfloat16 g_x2l[N2_TOT * C_IN];
__device__ __nv_bfloat16 g_W1h[C_OUT * C_OUT];
__device__ __nv_bfloat16 g_W1l[C_OUT * C_OUT];
__device__ __nv_bfloat16 g_W2h[C_OUT * C_IN];
__device__ __nv_bfloat16 g_W2l[C_OUT * C_IN];
__device__ float g_c1[C_OUT];
__device__ float g_c2[C_OUT];
// kNN scratch (SoA)
__device__ int   g_ki0[N1_TOT], g_ki1[N1_TOT], g_ki2[N1_TOT];
__device__ float g_kw0[N1_TOT], g_kw1[N1_TOT], g_kw2[N1_TOT];

// ---------------- cp.async helpers ----------------
__device__ __forceinline__ void cp_async16(uint32_t smem, const void* gptr) {
    asm volatile("cp.async.cg.shared.global [%0], [%1], 16;" :: "r"(smem), "l"(gptr));
}
__device__ __forceinline__ void cp_commit() {
    asm volatile("cp.async.commit_group;");
}
__device__ __forceinline__ void cp_wait0() {
    asm volatile("cp.async.wait_group 0;");
}

// -------- BN fold + bf16 split of weights ---------------------------------
template <int WHICH>
__global__ void fold_convert_W(const float* __restrict__ W, const float* __restrict__ b,
                               const float* __restrict__ g, const float* __restrict__ be,
                               const float* __restrict__ m, const float* __restrict__ v)
{
    const int Kd = (WHICH == 0) ? C_OUT : C_IN;
    __nv_bfloat16* Wh = (WHICH == 0) ? g_W1h : g_W2h;
    __nv_bfloat16* Wl = (WHICH == 0) ? g_W1l : g_W2l;
    float* cf = (WHICH == 0) ? g_c1 : g_c2;
    int n = blockIdx.x;
    float s = g[n] / sqrtf(v[n] + BN_EPS);
    if (threadIdx.x == 0) cf[n] = (b[n] - m[n]) * s + be[n];
    for (int k = threadIdx.x; k < Kd; k += blockDim.x) {
        float w = W[n * Kd + k] * s;
        __nv_bfloat16 h = __float2bfloat16(w);
        Wh[n * Kd + k] = h;
        Wl[n * Kd + k] = __float2bfloat16(w - __bfloat162float(h));
    }
}

// -------- bf16 split of activations (4 elements / thread — proven best) ----
__global__ void convert_x(const float* __restrict__ x,
                          __nv_bfloat16* __restrict__ xh,
                          __nv_bfloat16* __restrict__ xl, int n)
{
    int i = (blockIdx.x * blockDim.x + threadIdx.x) * 4;
    if (i >= n) return;
    float4 v = *(const float4*)(x + i);
    __nv_bfloat16 h0 = __float2bfloat16(v.x), h1 = __float2bfloat16(v.y);
    __nv_bfloat16 h2 = __float2bfloat16(v.z), h3 = __float2bfloat16(v.w);
    __nv_bfloat16 l0 = __float2bfloat16(v.x - __bfloat162float(h0));
    __nv_bfloat16 l1 = __float2bfloat16(v.y - __bfloat162float(h1));
    __nv_bfloat16 l2 = __float2bfloat16(v.z - __bfloat162float(h2));
    __nv_bfloat16 l3 = __float2bfloat16(v.w - __bfloat162float(h3));
    ushort4 ph = make_ushort4(__bfloat16_as_ushort(h0), __bfloat16_as_ushort(h1),
                              __bfloat16_as_ushort(h2), __bfloat16_as_ushort(h3));
    ushort4 pl = make_ushort4(__bfloat16_as_ushort(l0), __bfloat16_as_ushort(l1),
                              __bfloat16_as_ushort(l2), __bfloat16_as_ushort(l3));
    *(ushort4*)(xh + i) = ph;
    *(ushort4*)(xl + i) = pl;
}

// -------- tensor-core GEMM: C = relu( Ah*Bh + Ah*Bl + Al*Bh + bias ) ------
// (R8 proven core) For WHICH==0 the epilogue additionally fuses the kNN
// gather: out = relu(gemm + bias) + w0*h2[j0] + w1*h2[j1] + w2*h2[j2].
#define LDS_AB 40
#define LDS_C  132
#define TILE_ELEMS (128 * LDS_AB)

template <int WHICH>
__global__ __launch_bounds__(128) void gemm_wmma(float* __restrict__ Cout)
{
    constexpr int K = (WHICH == 0) ? C_OUT : C_IN;
    constexpr int NSTEP = K / 32;

    const __nv_bfloat16* __restrict__ Ah = (WHICH == 0) ? g_x1h : g_x2h;
    const __nv_bfloat16* __restrict__ Al = (WHICH == 0) ? g_x1l : g_x2l;
    const __nv_bfloat16* __restrict__ Bh = (WHICH == 0) ? g_W1h : g_W2h;
    const __nv_bfloat16* __restrict__ Bl = (WHICH == 0) ? g_W1l : g_W2l;
    const float* __restrict__ cb = (WHICH == 0) ? g_c1 : g_c2;
    float* __restrict__ Cp = (WHICH == 0) ? Cout : g_h2;

    extern __shared__ __align__(16) char smem_raw[];
    __nv_bfloat16* tiles = (__nv_bfloat16*)smem_raw;  // [2][4][TILE_ELEMS]
    float* Cs = (float*)smem_raw;                     // [128][132] (epilogue)

    const int tid = threadIdx.x;
    const int wid = tid >> 5;
    const int warp_m = wid >> 1;
    const int warp_n = wid & 1;
    const int bn = blockIdx.x * 128;
    const int bm = blockIdx.y * 128;

    wmma::fragment<wmma::accumulator, 16, 16, 16, float> acc[4][4];
#pragma unroll
    for (int i = 0; i < 4; i++)
#pragma unroll
        for (int j = 0; j < 4; j++) wmma::fill_fragment(acc[i][j], 0.0f);

    const uint32_t smem_base = (uint32_t)__cvta_generic_to_shared(tiles);

    auto load_tiles = [&](int s, int buf) {
        const int kk = s * 32;
        const uint32_t bufoff = (uint32_t)buf * 4 * TILE_ELEMS * 2;
#pragma unroll
        for (int j = 0; j < 16; j++) {
            int idx = tid + j * 128;
            int t   = idx >> 9;
            int w   = idx & 511;
            int r   = w >> 2;
            int c   = (w & 3) * 8;
            const __nv_bfloat16* src;
            if (t == 0)      src = Ah + (size_t)(bm + r) * K + kk + c;
            else if (t == 1) src = Al + (size_t)(bm + r) * K + kk + c;
            else if (t == 2) src = Bh + (size_t)(bn + r) * K + kk + c;
            else             src = Bl + (size_t)(bn + r) * K + kk + c;
            uint32_t dst = smem_base + bufoff +
                           (uint32_t)(t * TILE_ELEMS + r * LDS_AB + c) * 2;
            cp_async16(dst, src);
        }
        cp_commit();
    };

    load_tiles(0, 0);

    for (int s = 0; s < NSTEP; s++) {
        const int buf = s & 1;
        cp_wait0();
        __syncthreads();
        if (s + 1 < NSTEP) load_tiles(s + 1, buf ^ 1);

        const __nv_bfloat16* tAh = tiles + (size_t)buf * 4 * TILE_ELEMS;
        const __nv_bfloat16* tAl = tAh + TILE_ELEMS;
        const __nv_bfloat16* tBh = tAl + TILE_ELEMS;
        const __nv_bfloat16* tBl = tBh + TILE_ELEMS;

#pragma unroll
        for (int kf = 0; kf < 2; kf++) {
            wmma::fragment<wmma::matrix_a, 16, 16, 16, __nv_bfloat16, wmma::row_major> af[4];
            wmma::fragment<wmma::matrix_b, 16, 16, 16, __nv_bfloat16, wmma::col_major> bfh[4], bfl[4];
#pragma unroll
            for (int i = 0; i < 4; i++)
                wmma::load_matrix_sync(af[i], tAh + (warp_m * 64 + i * 16) * LDS_AB + kf * 16, LDS_AB);
#pragma unroll
            for (int j = 0; j < 4; j++) {
                wmma::load_matrix_sync(bfh[j], tBh + (warp_n * 64 + j * 16) * LDS_AB + kf * 16, LDS_AB);
                wmma::load_matrix_sync(bfl[j], tBl + (warp_n * 64 + j * 16) * LDS_AB + kf * 16, LDS_AB);
            }
#pragma unroll
            for (int i = 0; i < 4; i++)
#pragma unroll
                for (int j = 0; j < 4; j++) {
                    wmma::mma_sync(acc[i][j], af[i], bfh[j], acc[i][j]);
                    wmma::mma_sync(acc[i][j], af[i], bfl[j], acc[i][j]);
                }
#pragma unroll
            for (int i = 0; i < 4; i++)
                wmma::load_matrix_sync(af[i], tAl + (warp_m * 64 + i * 16) * LDS_AB + kf * 16, LDS_AB);
#pragma unroll
            for (int i = 0; i < 4; i++)
#pragma unroll
                for (int j = 0; j < 4; j++)
                    wmma::mma_sync(acc[i][j], af[i], bfh[j], acc[i][j]);
        }
        __syncthreads();
    }

#pragma unroll
    for (int i = 0; i < 4; i++)
#pragma unroll
        for (int j = 0; j < 4; j++)
            wmma::store_matrix_sync(Cs + (warp_m * 64 + i * 16) * LDS_C + warp_n * 64 + j * 16,
                                    acc[i][j], LDS_C, wmma::mem_row_major);
    __syncthreads();

    if constexpr (WHICH == 0) {
        // fused epilogue: relu(gemm+bias) + kNN-weighted h2 rows -> out
        const unsigned full = 0xffffffffu;
        const int warp = tid >> 5, lane = tid & 31;
        const int scene = bm / N1_PER;              // constant per CTA
        const int h2base = scene * N2_PER;
        const int q = bm + tid;                     // this thread's query
        const int i0 = g_ki0[q], i1 = g_ki1[q], i2 = g_ki2[q];
        const float w0 = g_kw0[q], w1 = g_kw1[q], w2 = g_kw2[q];
        const float4 bv = *(const float4*)(cb + bn + lane * 4);

        for (int s = 0; s < 32; s++) {
            float ww0 = __shfl_sync(full, w0, s);
            float ww1 = __shfl_sync(full, w1, s);
            float ww2 = __shfl_sync(full, w2, s);
            int   j0  = __shfl_sync(full, i0, s);
            int   j1  = __shfl_sync(full, i1, s);
            int   j2  = __shfl_sync(full, i2, s);
            const int row = warp * 32 + s;
            const float4 a = ((const float4*)(g_h2 + (size_t)(h2base + j0) * 256 + bn))[lane];
            const float4 b = ((const float4*)(g_h2 + (size_t)(h2base + j1) * 256 + bn))[lane];
            const float4 c = ((const float4*)(g_h2 + (size_t)(h2base + j2) * 256 + bn))[lane];
            const float4 cs4 = *(const float4*)(Cs + row * LDS_C + lane * 4);
            float4 v;
            v.x = fmaxf(cs4.x + bv.x, 0.f) + ww0 * a.x + ww1 * b.x + ww2 * c.x;
            v.y = fmaxf(cs4.y + bv.y, 0.f) + ww0 * a.y + ww1 * b.y + ww2 * c.y;
            v.z = fmaxf(cs4.z + bv.z, 0.f) + ww0 * a.z + ww1 * b.z + ww2 * c.z;
            v.w = fmaxf(cs4.w + bv.w, 0.f) + ww0 * a.w + ww1 * b.w + ww2 * c.w;
            *(float4*)(Cp + (size_t)(bm + row) * 256 + bn + lane * 4) = v;
        }
    } else {
        const int r = tid;
        const float* csrow = Cs + r * LDS_C;
        float* orow = Cp + (size_t)(bm + r) * 256 + bn;
#pragma unroll
        for (int t = 0; t < 32; t++) {
            float4 v = *(const float4*)(csrow + t * 4);
            float4 bv = *(const float4*)(cb + bn + t * 4);
            v.x = fmaxf(v.x + bv.x, 0.f);
            v.y = fmaxf(v.y + bv.y, 0.f);
            v.z = fmaxf(v.z + bv.z, 0.f);
            v.w = fmaxf(v.w + bv.w, 0.f);
            *(float4*)(orow + t * 4) = v;
        }
    }
}

#define GEMM_SMEM (8 * TILE_ELEMS * 2 > 128 * LDS_C * 4 ? 8 * TILE_ELEMS * 2 : 128 * LDS_C * 4)

// ---------------- kNN select: split-scan (2 threads / query) ---------------
// 512 threads, 256 queries per block. Thread (qloc, half) scans candidates
// [half*2048, half*2048+2048). Upper half publishes its top-3 via smem;
// lower half merges (strict < keeps lower indices on ties -> reference
// tie order preserved) and writes indices + normalized weights.
#define TOP3_UPD(s, kk, A0, A1, A2, I0, I1, I2)            \
    if (s < A2) {                                          \
        if (s < A1) {                                      \
            A2 = A1; I2 = I1;                              \
            if (s < A0) { A1 = A0; I1 = I0; A0 = s; I0 = kk; } \
            else        { A1 = s;  I1 = kk; }              \
        } else { A2 = s; I2 = kk; }                        \
    }

#define SEL_SMEM (N2_PER * 16 + 256 * 3 * 4 * 2)

__global__ __launch_bounds__(512) void knn_select_kernel(
    const float* __restrict__ p1, const float* __restrict__ p2)
{
    extern __shared__ __align__(16) char sm[];
    float4* pts = (float4*)sm;                       // [4096]
    float*  mb  = (float*)(sm + N2_PER * 16);        // [3][256] upper dists
    int*    mi  = (int*)(sm + N2_PER * 16 + 3072);   // [3][256] upper idx

    const int scene = blockIdx.y;
    const int tid   = threadIdx.x;
    const int qloc  = tid & 255;
    const int half  = tid >> 8;

    const float* p2s = p2 + (size_t)scene * N2_PER * 3;
    for (int i = tid; i < N2_PER; i += 512) {
        pts[i] = make_float4(p2s[3 * i + 0], p2s[3 * i + 1], p2s[3 * i + 2], 0.f);
    }
    __syncthreads();

    const int q = scene * N1_PER + blockIdx.x * 256 + qloc;
    const float qx = p1[3 * q + 0];
    const float qy = p1[3 * q + 1];
    const float qz = p1[3 * q + 2];

    float b0 = 3.4e38f, b1 = 3.4e38f, b2 = 3.4e38f;
    int   i0 = 0, i1 = 0, i2 = 0;

    const int kbeg = half * (N2_PER / 2);
    const int kend = kbeg + (N2_PER / 2);
#pragma unroll 2
    for (int k = kbeg; k < kend; k += 4) {
        float4 pa = pts[k + 0];
        float4 pb = pts[k + 1];
        float4 pc = pts[k + 2];
        float4 pd = pts[k + 3];
        float dxa = qx - pa.x, dya = qy - pa.y, dza = qz - pa.z;
        float da  = fmaf(dxa, dxa, fmaf(dya, dya, dza * dza));
        float dxb = qx - pb.x, dyb = qy - pb.y, dzb = qz - pb.z;
        float db  = fmaf(dxb, dxb, fmaf(dyb, dyb, dzb * dzb));
        float dxc = qx - pc.x, dyc = qy - pc.y, dzc = qz - pc.z;
        float dc  = fmaf(dxc, dxc, fmaf(dyc, dyc, dzc * dzc));
        float dxd = qx - pd.x, dyd = qy - pd.y, dzd = qz - pd.z;
        float dd  = fmaf(dxd, dxd, fmaf(dyd, dyd, dzd * dzd));
        float m = fminf(fminf(da, db), fminf(dc, dd));
        if (m < b2) {
            TOP3_UPD(da, k + 0, b0, b1, b2, i0, i1, i2);
            TOP3_UPD(db, k + 1, b0, b1, b2, i0, i1, i2);
            TOP3_UPD(dc, k + 2, b0, b1, b2, i0, i1, i2);
            TOP3_UPD(dd, k + 3, b0, b1, b2, i0, i1, i2);
        }
    }

    if (half == 1) {
        mb[0 * 256 + qloc] = b0; mi[0 * 256 + qloc] = i0;
        mb[1 * 256 + qloc] = b1; mi[1 * 256 + qloc] = i1;
        mb[2 * 256 + qloc] = b2; mi[2 * 256 + qloc] = i2;
    }
    __syncthreads();

    if (half == 0) {
        // merge upper half's 3 candidates (ascending order preserved)
#pragma unroll
        for (int t = 0; t < 3; t++) {
            float d = mb[t * 256 + qloc];
            int   ii = mi[t * 256 + qloc];
            TOP3_UPD(d, ii, b0, b1, b2, i0, i1, i2);
        }

        float w0 = 1.f / (sqrtf(fmaxf(b0, 1e-12f)) + 1e-8f);
        float w1 = 1.f / (sqrtf(fmaxf(b1, 1e-12f)) + 1e-8f);
        float w2 = 1.f / (sqrtf(fmaxf(b2, 1e-12f)) + 1e-8f);
        float ws = w0 + w1 + w2;

        g_ki0[q] = i0; g_ki1[q] = i1; g_ki2[q] = i2;
        g_kw0[q] = w0 / ws; g_kw1[q] = w1 / ws; g_kw2[q] = w2 / ws;
    }
}

// ---------------- launch -----------------
extern "C" void kernel_launch(void* const* d_in, const int* in_sizes, int n_in,
                              void* d_out, int out_size)
{
    const float* p1  = (const float*)d_in[0];
    const float* x1  = (const float*)d_in[1];
    const float* p2  = (const float*)d_in[2];
    const float* x2  = (const float*)d_in[3];
    const float* W1  = (const float*)d_in[4];
    const float* b1  = (const float*)d_in[5];
    const float* g1  = (const float*)d_in[6];
    const float* be1 = (const float*)d_in[7];
    const float* m1  = (const float*)d_in[8];
    const float* v1  = (const float*)d_in[9];
    const float* W2  = (const float*)d_in[10];
    const float* b2  = (const float*)d_in[11];
    const float* g2  = (const float*)d_in[12];
    const float* be2 = (const float*)d_in[13];
    const float* m2  = (const float*)d_in[14];
    const float* v2  = (const float*)d_in[15];
    float* out = (float*)d_out;

    static bool init_done = false;
    static cudaStream_t s2 = nullptr, s3 = nullptr;
    static cudaEvent_t evFork = nullptr, evSel = nullptr, evCx1 = nullptr;
    if (!init_done) {
        cudaFuncSetAttribute(gemm_wmma<0>, cudaFuncAttributeMaxDynamicSharedMemorySize, GEMM_SMEM);
        cudaFuncSetAttribute(gemm_wmma<1>, cudaFuncAttributeMaxDynamicSharedMemorySize, GEMM_SMEM);
        cudaFuncSetAttribute(knn_select_kernel, cudaFuncAttributeMaxDynamicSharedMemorySize,
                             SEL_SMEM);
        cudaStreamCreateWithFlags(&s2, cudaStreamNonBlocking);
        cudaStreamCreateWithFlags(&s3, cudaStreamNonBlocking);
        cudaEventCreateWithFlags(&evFork, cudaEventDisableTiming);
        cudaEventCreateWithFlags(&evSel, cudaEventDisableTiming);
        cudaEventCreateWithFlags(&evCx1, cudaEventDisableTiming);
        init_done = true;
    }

    __nv_bfloat16 *x1h, *x1l, *x2h, *x2l;
    cudaGetSymbolAddress((void**)&x1h, g_x1h);
    cudaGetSymbolAddress((void**)&x1l, g_x1l);
    cudaGetSymbolAddress((void**)&x2h, g_x2h);
    cudaGetSymbolAddress((void**)&x2l, g_x2l);

    // ---- fork ----
    cudaEventRecord(evFork, 0);
    cudaStreamWaitEvent(s2, evFork, 0);
    cudaStreamWaitEvent(s3, evFork, 0);

    // s2: kNN selection (split-scan)
    {
        dim3 gridk(N1_PER / 256, BATCH);
        knn_select_kernel<<<gridk, 512, SEL_SMEM, s2>>>(p1, p2);
    }
    cudaEventRecord(evSel, s2);

    // s3: convert x1 (only needed by gemm<0>)
    {
        int n1 = N1_TOT * C_OUT;
        convert_x<<<n1 / 4 / 256, 256, 0, s3>>>(x1, x1h, x1l, n1);
    }
    cudaEventRecord(evCx1, s3);

    // ---- main stream: fold + convert_x2 + gemm<1> (h2) ----
    fold_convert_W<0><<<C_OUT, 128>>>(W1, b1, g1, be1, m1, v1);
    fold_convert_W<1><<<C_OUT, 128>>>(W2, b2, g2, be2, m2, v2);
    {
        int n2 = N2_TOT * C_IN;
        convert_x<<<n2 / 4 / 256, 256>>>(x2, x2h, x2l, n2);
    }
    {
        dim3 grid2(2, N2_TOT / 128);
        gemm_wmma<1><<<grid2, 128, GEMM_SMEM>>>(out);
    }

    // ---- join: gemm<0> fused epilogue needs select + x1 conversion ----
    cudaStreamWaitEvent(0, evSel, 0);
    cudaStreamWaitEvent(0, evCx1, 0);

    // out = relu(bn(x1@W1^T)) + kNN-interp(h2)  (fused)
    {
        dim3 grid1(2, N1_TOT / 128);
        gemm_wmma<0><<<grid1, 128, GEMM_SMEM>>>(out);
    }
}

// round 13
// speedup vs baseline: 2.0550x; 1.0188x over previous
#include <cuda_runtime.h>
#include <cuda_bf16.h>
#include <mma.h>
#include <cstdint>

using namespace nvcuda;

// ---------------- problem constants ----------------
#define BATCH      4
#define N1_PER     16384
#define N2_PER     4096
#define N1_TOT     (BATCH * N1_PER)    // 65536
#define N2_TOT     (BATCH * N2_PER)    // 16384
#define C_IN       512
#define C_OUT      256
#define BN_EPS     1e-5f

// ---------------- device scratch (static, allocation-free) ----------------
__device__ float g_h2[N2_TOT * C_OUT];                    // 16 MB
__device__ __nv_bfloat16 g_x1h[N1_TOT * C_OUT];
__device__ __nv_bfloat16 g_x1l[N1_TOT * C_OUT];
__device__ __nv_bfloat16 g_x2h[N2_TOT * C_IN];
__device__ __nv_bfloat16 g_x2l[N2_TOT * C_IN];
__device__ __nv_bfloat16 g_W1h[C_OUT * C_OUT];
__device__ __nv_bfloat16 g_W1l[C_OUT * C_OUT];
__device__ __nv_bfloat16 g_W2h[C_OUT * C_IN];
__device__ __nv_bfloat16 g_W2l[C_OUT * C_IN];
__device__ float g_c1[C_OUT];
__device__ float g_c2[C_OUT];
// kNN scratch (SoA)
__device__ int   g_ki0[N1_TOT], g_ki1[N1_TOT], g_ki2[N1_TOT];
__device__ float g_kw0[N1_TOT], g_kw1[N1_TOT], g_kw2[N1_TOT];
// device-side join flags (zeroed every launch/replay)
__device__ int g_h2_done;
__device__ int g_sel_done;

__global__ void zero_flags_kernel() { g_h2_done = 0; g_sel_done = 0; }

// ---------------- cp.async helpers ----------------
__device__ __forceinline__ void cp_async16(uint32_t smem, const void* gptr) {
    asm volatile("cp.async.cg.shared.global [%0], [%1], 16;" :: "r"(smem), "l"(gptr));
}
__device__ __forceinline__ void cp_commit() {
    asm volatile("cp.async.commit_group;");
}
__device__ __forceinline__ void cp_wait0() {
    asm volatile("cp.async.wait_group 0;");
}

// -------- BN fold + bf16 split of BOTH weight matrices (one launch) -------
__global__ void fold_convert_Wboth(
    const float* __restrict__ W1, const float* __restrict__ b1,
    const float* __restrict__ g1, const float* __restrict__ be1,
    const float* __restrict__ m1, const float* __restrict__ v1,
    const float* __restrict__ W2, const float* __restrict__ b2,
    const float* __restrict__ g2, const float* __restrict__ be2,
    const float* __restrict__ m2, const float* __restrict__ v2)
{
    const int which = (blockIdx.x >= 256);
    const int n = blockIdx.x & 255;
    const int Kd = which ? C_IN : C_OUT;
    const float* W  = which ? W2 : W1;
    const float* b  = which ? b2 : b1;
    const float* g  = which ? g2 : g1;
    const float* be = which ? be2 : be1;
    const float* m  = which ? m2 : m1;
    const float* v  = which ? v2 : v1;
    __nv_bfloat16* Wh = which ? g_W2h : g_W1h;
    __nv_bfloat16* Wl = which ? g_W2l : g_W1l;
    float* cf = which ? g_c2 : g_c1;

    float s = g[n] / sqrtf(v[n] + BN_EPS);
    if (threadIdx.x == 0) cf[n] = (b[n] - m[n]) * s + be[n];
    for (int k = threadIdx.x; k < Kd; k += blockDim.x) {
        float w = W[n * Kd + k] * s;
        __nv_bfloat16 h = __float2bfloat16(w);
        Wh[n * Kd + k] = h;
        Wl[n * Kd + k] = __float2bfloat16(w - __bfloat162float(h));
    }
}

// -------- bf16 split of activations (4 elements / thread — proven best) ----
__global__ void convert_x(const float* __restrict__ x,
                          __nv_bfloat16* __restrict__ xh,
                          __nv_bfloat16* __restrict__ xl, int n)
{
    int i = (blockIdx.x * blockDim.x + threadIdx.x) * 4;
    if (i >= n) return;
    float4 v = *(const float4*)(x + i);
    __nv_bfloat16 h0 = __float2bfloat16(v.x), h1 = __float2bfloat16(v.y);
    __nv_bfloat16 h2 = __float2bfloat16(v.z), h3 = __float2bfloat16(v.w);
    __nv_bfloat16 l0 = __float2bfloat16(v.x - __bfloat162float(h0));
    __nv_bfloat16 l1 = __float2bfloat16(v.y - __bfloat162float(h1));
    __nv_bfloat16 l2 = __float2bfloat16(v.z - __bfloat162float(h2));
    __nv_bfloat16 l3 = __float2bfloat16(v.w - __bfloat162float(h3));
    ushort4 ph = make_ushort4(__bfloat16_as_ushort(h0), __bfloat16_as_ushort(h1),
                              __bfloat16_as_ushort(h2), __bfloat16_as_ushort(h3));
    ushort4 pl = make_ushort4(__bfloat16_as_ushort(l0), __bfloat16_as_ushort(l1),
                              __bfloat16_as_ushort(l2), __bfloat16_as_ushort(l3));
    *(ushort4*)(xh + i) = ph;
    *(ushort4*)(xl + i) = pl;
}

// -------- tensor-core GEMM body (R8 proven core) --------------------------
// WHICH==1: h2 = relu(bn(x2@W2^T)) -> g_h2
// WHICH==0: out = relu(bn(x1@W1^T)) + kNN-interp (spin-waits device flags)
#define LDS_AB 40
#define LDS_C  132
#define TILE_ELEMS (128 * LDS_AB)

template <int WHICH>
__device__ __forceinline__ void gemm_body(const int bn, const int bm, float* __restrict__ Cout)
{
    constexpr int K = (WHICH == 0) ? C_OUT : C_IN;
    constexpr int NSTEP = K / 32;

    const __nv_bfloat16* __restrict__ Ah = (WHICH == 0) ? g_x1h : g_x2h;
    const __nv_bfloat16* __restrict__ Al = (WHICH == 0) ? g_x1l : g_x2l;
    const __nv_bfloat16* __restrict__ Bh = (WHICH == 0) ? g_W1h : g_W2h;
    const __nv_bfloat16* __restrict__ Bl = (WHICH == 0) ? g_W1l : g_W2l;
    const float* __restrict__ cb = (WHICH == 0) ? g_c1 : g_c2;
    float* __restrict__ Cp = (WHICH == 0) ? Cout : g_h2;

    extern __shared__ __align__(16) char smem_raw[];
    __nv_bfloat16* tiles = (__nv_bfloat16*)smem_raw;  // [2][4][TILE_ELEMS]
    float* Cs = (float*)smem_raw;                     // [128][132] (epilogue)

    const int tid = threadIdx.x;
    const int wid = tid >> 5;
    const int warp_m = wid >> 1;
    const int warp_n = wid & 1;

    wmma::fragment<wmma::accumulator, 16, 16, 16, float> acc[4][4];
#pragma unroll
    for (int i = 0; i < 4; i++)
#pragma unroll
        for (int j = 0; j < 4; j++) wmma::fill_fragment(acc[i][j], 0.0f);

    const uint32_t smem_base = (uint32_t)__cvta_generic_to_shared(tiles);

    auto load_tiles = [&](int s, int buf) {
        const int kk = s * 32;
        const uint32_t bufoff = (uint32_t)buf * 4 * TILE_ELEMS * 2;
#pragma unroll
        for (int j = 0; j < 16; j++) {
            int idx = tid + j * 128;
            int t   = idx >> 9;
            int w   = idx & 511;
            int r   = w >> 2;
            int c   = (w & 3) * 8;
            const __nv_bfloat16* src;
            if (t == 0)      src = Ah + (size_t)(bm + r) * K + kk + c;
            else if (t == 1) src = Al + (size_t)(bm + r) * K + kk + c;
            else if (t == 2) src = Bh + (size_t)(bn + r) * K + kk + c;
            else             src = Bl + (size_t)(bn + r) * K + kk + c;
            uint32_t dst = smem_base + bufoff +
                           (uint32_t)(t * TILE_ELEMS + r * LDS_AB + c) * 2;
            cp_async16(dst, src);
        }
        cp_commit();
    };

    load_tiles(0, 0);

    for (int s = 0; s < NSTEP; s++) {
        const int buf = s & 1;
        cp_wait0();
        __syncthreads();
        if (s + 1 < NSTEP) load_tiles(s + 1, buf ^ 1);

        const __nv_bfloat16* tAh = tiles + (size_t)buf * 4 * TILE_ELEMS;
        const __nv_bfloat16* tAl = tAh + TILE_ELEMS;
        const __nv_bfloat16* tBh = tAl + TILE_ELEMS;
        const __nv_bfloat16* tBl = tBh + TILE_ELEMS;

#pragma unroll
        for (int kf = 0; kf < 2; kf++) {
            wmma::fragment<wmma::matrix_a, 16, 16, 16, __nv_bfloat16, wmma::row_major> af[4];
            wmma::fragment<wmma::matrix_b, 16, 16, 16, __nv_bfloat16, wmma::col_major> bfh[4], bfl[4];
#pragma unroll
            for (int i = 0; i < 4; i++)
                wmma::load_matrix_sync(af[i], tAh + (warp_m * 64 + i * 16) * LDS_AB + kf * 16, LDS_AB);
#pragma unroll
            for (int j = 0; j < 4; j++) {
                wmma::load_matrix_sync(bfh[j], tBh + (warp_n * 64 + j * 16) * LDS_AB + kf * 16, LDS_AB);
                wmma::load_matrix_sync(bfl[j], tBl + (warp_n * 64 + j * 16) * LDS_AB + kf * 16, LDS_AB);
            }
#pragma unroll
            for (int i = 0; i < 4; i++)
#pragma unroll
                for (int j = 0; j < 4; j++) {
                    wmma::mma_sync(acc[i][j], af[i], bfh[j], acc[i][j]);
                    wmma::mma_sync(acc[i][j], af[i], bfl[j], acc[i][j]);
                }
#pragma unroll
            for (int i = 0; i < 4; i++)
                wmma::load_matrix_sync(af[i], tAl + (warp_m * 64 + i * 16) * LDS_AB + kf * 16, LDS_AB);
#pragma unroll
            for (int i = 0; i < 4; i++)
#pragma unroll
                for (int j = 0; j < 4; j++)
                    wmma::mma_sync(acc[i][j], af[i], bfh[j], acc[i][j]);
        }
        __syncthreads();
    }

#pragma unroll
    for (int i = 0; i < 4; i++)
#pragma unroll
        for (int j = 0; j < 4; j++)
            wmma::store_matrix_sync(Cs + (warp_m * 64 + i * 16) * LDS_C + warp_n * 64 + j * 16,
                                    acc[i][j], LDS_C, wmma::mem_row_major);
    __syncthreads();

    if constexpr (WHICH == 0) {
        // device-side join: wait for h2 (256 CTAs) + select (256 CTAs)
        if (tid == 0) {
            volatile int* ph = &g_h2_done;
            volatile int* ps = &g_sel_done;
            while (*ph < 256 || *ps < 256) __nanosleep(128);
            __threadfence();
        }
        __syncthreads();

        // fused epilogue: relu(gemm+bias) + kNN-weighted h2 rows -> out
        const unsigned full = 0xffffffffu;
        const int warp = tid >> 5, lane = tid & 31;
        const int scene = bm / N1_PER;
        const int h2base = scene * N2_PER;
        const int q = bm + tid;
        const int i0 = g_ki0[q], i1 = g_ki1[q], i2 = g_ki2[q];
        const float w0 = g_kw0[q], w1 = g_kw1[q], w2 = g_kw2[q];
        const float4 bv = *(const float4*)(cb + bn + lane * 4);

        for (int s = 0; s < 32; s++) {
            float ww0 = __shfl_sync(full, w0, s);
            float ww1 = __shfl_sync(full, w1, s);
            float ww2 = __shfl_sync(full, w2, s);
            int   j0  = __shfl_sync(full, i0, s);
            int   j1  = __shfl_sync(full, i1, s);
            int   j2  = __shfl_sync(full, i2, s);
            const int row = warp * 32 + s;
            const float4 a = ((const float4*)(g_h2 + (size_t)(h2base + j0) * 256 + bn))[lane];
            const float4 b = ((const float4*)(g_h2 + (size_t)(h2base + j1) * 256 + bn))[lane];
            const float4 c = ((const float4*)(g_h2 + (size_t)(h2base + j2) * 256 + bn))[lane];
            const float4 cs4 = *(const float4*)(Cs + row * LDS_C + lane * 4);
            float4 v;
            v.x = fmaxf(cs4.x + bv.x, 0.f) + ww0 * a.x + ww1 * b.x + ww2 * c.x;
            v.y = fmaxf(cs4.y + bv.y, 0.f) + ww0 * a.y + ww1 * b.y + ww2 * c.y;
            v.z = fmaxf(cs4.z + bv.z, 0.f) + ww0 * a.z + ww1 * b.z + ww2 * c.z;
            v.w = fmaxf(cs4.w + bv.w, 0.f) + ww0 * a.w + ww1 * b.w + ww2 * c.w;
            *(float4*)(Cp + (size_t)(bm + row) * 256 + bn + lane * 4) = v;
        }
    } else {
        const int r = tid;
        const float* csrow = Cs + r * LDS_C;
        float* orow = Cp + (size_t)(bm + r) * 256 + bn;
#pragma unroll
        for (int t = 0; t < 32; t++) {
            float4 v = *(const float4*)(csrow + t * 4);
            float4 bv = *(const float4*)(cb + bn + t * 4);
            v.x = fmaxf(v.x + bv.x, 0.f);
            v.y = fmaxf(v.y + bv.y, 0.f);
            v.z = fmaxf(v.z + bv.z, 0.f);
            v.w = fmaxf(v.w + bv.w, 0.f);
            *(float4*)(orow + t * 4) = v;
        }
    }
}

// Merged launch: bids 0..255 = gemm<1> (h2), bids 256..1279 = gemm<0> (out).
// Low bids dispatch first -> gemm<1> role is never starved by spinners.
__global__ __launch_bounds__(128) void gemm_merged(float* __restrict__ out)
{
    const int bid = blockIdx.x;
    if (bid < 256) {
        gemm_body<1>((bid & 1) * 128, (bid >> 1) * 128, out);
        __syncthreads();
        if (threadIdx.x == 0) {
            __threadfence();
            atomicAdd(&g_h2_done, 1);
        }
    } else {
        const int b = bid - 256;
        gemm_body<0>((b & 1) * 128, (b >> 1) * 128, out);
    }
}

#define GEMM_SMEM (8 * TILE_ELEMS * 2 > 128 * LDS_C * 4 ? 8 * TILE_ELEMS * 2 : 128 * LDS_C * 4)

// ---------------- kNN select: split-scan (2 threads / query) ---------------
#define TOP3_UPD(s, kk, A0, A1, A2, I0, I1, I2)            \
    if (s < A2) {                                          \
        if (s < A1) {                                      \
            A2 = A1; I2 = I1;                              \
            if (s < A0) { A1 = A0; I1 = I0; A0 = s; I0 = kk; } \
            else        { A1 = s;  I1 = kk; }              \
        } else { A2 = s; I2 = kk; }                        \
    }

#define SEL_SMEM (N2_PER * 16 + 256 * 3 * 4 * 2)

__global__ __launch_bounds__(512) void knn_select_kernel(
    const float* __restrict__ p1, const float* __restrict__ p2)
{
    extern __shared__ __align__(16) char sm[];
    float4* pts = (float4*)sm;                       // [4096]
    float*  mb  = (float*)(sm + N2_PER * 16);        // [3][256] upper dists
    int*    mi  = (int*)(sm + N2_PER * 16 + 3072);   // [3][256] upper idx

    const int scene = blockIdx.y;
    const int tid   = threadIdx.x;
    const int qloc  = tid & 255;
    const int half  = tid >> 8;

    const float* p2s = p2 + (size_t)scene * N2_PER * 3;
    for (int i = tid; i < N2_PER; i += 512) {
        pts[i] = make_float4(p2s[3 * i + 0], p2s[3 * i + 1], p2s[3 * i + 2], 0.f);
    }
    __syncthreads();

    const int q = scene * N1_PER + blockIdx.x * 256 + qloc;
    const float qx = p1[3 * q + 0];
    const float qy = p1[3 * q + 1];
    const float qz = p1[3 * q + 2];

    float b0 = 3.4e38f, b1 = 3.4e38f, b2 = 3.4e38f;
    int   i0 = 0, i1 = 0, i2 = 0;

    const int kbeg = half * (N2_PER / 2);
    const int kend = kbeg + (N2_PER / 2);
#pragma unroll 2
    for (int k = kbeg; k < kend; k += 4) {
        float4 pa = pts[k + 0];
        float4 pb = pts[k + 1];
        float4 pc = pts[k + 2];
        float4 pd = pts[k + 3];
        float dxa = qx - pa.x, dya = qy - pa.y, dza = qz - pa.z;
        float da  = fmaf(dxa, dxa, fmaf(dya, dya, dza * dza));
        float dxb = qx - pb.x, dyb = qy - pb.y, dzb = qz - pb.z;
        float db  = fmaf(dxb, dxb, fmaf(dyb, dyb, dzb * dzb));
        float dxc = qx - pc.x, dyc = qy - pc.y, dzc = qz - pc.z;
        float dc  = fmaf(dxc, dxc, fmaf(dyc, dyc, dzc * dzc));
        float dxd = qx - pd.x, dyd = qy - pd.y, dzd = qz - pd.z;
        float dd  = fmaf(dxd, dxd, fmaf(dyd, dyd, dzd * dzd));
        float m = fminf(fminf(da, db), fminf(dc, dd));
        if (m < b2) {
            TOP3_UPD(da, k + 0, b0, b1, b2, i0, i1, i2);
            TOP3_UPD(db, k + 1, b0, b1, b2, i0, i1, i2);
            TOP3_UPD(dc, k + 2, b0, b1, b2, i0, i1, i2);
            TOP3_UPD(dd, k + 3, b0, b1, b2, i0, i1, i2);
        }
    }

    if (half == 1) {
        mb[0 * 256 + qloc] = b0; mi[0 * 256 + qloc] = i0;
        mb[1 * 256 + qloc] = b1; mi[1 * 256 + qloc] = i1;
        mb[2 * 256 + qloc] = b2; mi[2 * 256 + qloc] = i2;
    }
    __syncthreads();

    if (half == 0) {
#pragma unroll
        for (int t = 0; t < 3; t++) {
            float d = mb[t * 256 + qloc];
            int   ii = mi[t * 256 + qloc];
            TOP3_UPD(d, ii, b0, b1, b2, i0, i1, i2);
        }

        float w0 = 1.f / (sqrtf(fmaxf(b0, 1e-12f)) + 1e-8f);
        float w1 = 1.f / (sqrtf(fmaxf(b1, 1e-12f)) + 1e-8f);
        float w2 = 1.f / (sqrtf(fmaxf(b2, 1e-12f)) + 1e-8f);
        float ws = w0 + w1 + w2;

        g_ki0[q] = i0; g_ki1[q] = i1; g_ki2[q] = i2;
        g_kw0[q] = w0 / ws; g_kw1[q] = w1 / ws; g_kw2[q] = w2 / ws;
    }

    __syncthreads();
    if (tid == 0) {
        __threadfence();
        atomicAdd(&g_sel_done, 1);
    }
}

// ---------------- launch -----------------
extern "C" void kernel_launch(void* const* d_in, const int* in_sizes, int n_in,
                              void* d_out, int out_size)
{
    const float* p1  = (const float*)d_in[0];
    const float* x1  = (const float*)d_in[1];
    const float* p2  = (const float*)d_in[2];
    const float* x2  = (const float*)d_in[3];
    const float* W1  = (const float*)d_in[4];
    const float* b1  = (const float*)d_in[5];
    const float* g1  = (const float*)d_in[6];
    const float* be1 = (const float*)d_in[7];
    const float* m1  = (const float*)d_in[8];
    const float* v1  = (const float*)d_in[9];
    const float* W2  = (const float*)d_in[10];
    const float* b2  = (const float*)d_in[11];
    const float* g2  = (const float*)d_in[12];
    const float* be2 = (const float*)d_in[13];
    const float* m2  = (const float*)d_in[14];
    const float* v2  = (const float*)d_in[15];
    float* out = (float*)d_out;

    static bool init_done = false;
    static cudaStream_t s2 = nullptr, s3 = nullptr;
    static cudaEvent_t evFork = nullptr, evSel = nullptr, evCx1 = nullptr;
    if (!init_done) {
        cudaFuncSetAttribute(gemm_merged, cudaFuncAttributeMaxDynamicSharedMemorySize, GEMM_SMEM);
        cudaFuncSetAttribute(knn_select_kernel, cudaFuncAttributeMaxDynamicSharedMemorySize,
                             SEL_SMEM);
        cudaStreamCreateWithFlags(&s2, cudaStreamNonBlocking);
        cudaStreamCreateWithFlags(&s3, cudaStreamNonBlocking);
        cudaEventCreateWithFlags(&evFork, cudaEventDisableTiming);
        cudaEventCreateWithFlags(&evSel, cudaEventDisableTiming);
        cudaEventCreateWithFlags(&evCx1, cudaEventDisableTiming);
        init_done = true;
    }

    __nv_bfloat16 *x1h, *x1l, *x2h, *x2l;
    cudaGetSymbolAddress((void**)&x1h, g_x1h);
    cudaGetSymbolAddress((void**)&x1l, g_x1l);
    cudaGetSymbolAddress((void**)&x2h, g_x2h);
    cudaGetSymbolAddress((void**)&x2l, g_x2l);

    // ---- zero flags, then fork ----
    zero_flags_kernel<<<1, 1>>>();
    cudaEventRecord(evFork, 0);
    cudaStreamWaitEvent(s2, evFork, 0);
    cudaStreamWaitEvent(s3, evFork, 0);

    // s2: kNN selection (signals g_sel_done via device flag)
    {
        dim3 gridk(N1_PER / 256, BATCH);
        knn_select_kernel<<<gridk, 512, SEL_SMEM, s2>>>(p1, p2);
    }
    cudaEventRecord(evSel, s2);

    // s3: convert x1 (needed by gemm<0> mainloop)
    {
        int n1 = N1_TOT * C_OUT;
        convert_x<<<n1 / 4 / 256, 256, 0, s3>>>(x1, x1h, x1l, n1);
    }
    cudaEventRecord(evCx1, s3);

    // ---- main stream: fused folds + convert_x2 ----
    fold_convert_Wboth<<<512, 128>>>(W1, b1, g1, be1, m1, v1,
                                     W2, b2, g2, be2, m2, v2);
    {
        int n2 = N2_TOT * C_IN;
        convert_x<<<n2 / 4 / 256, 256>>>(x2, x2h, x2l, n2);
    }

    // merged GEMM needs x1 conversion done (stream-ordered); h2+select are
    // joined on-device via flags.
    cudaStreamWaitEvent(0, evCx1, 0);
    gemm_merged<<<1280, 128, GEMM_SMEM>>>(out);

    // join s2 into the origin stream AFTER the gemm launch: closes the
    // capture graph without serializing gemm behind select (the real data
    // dependency is enforced on-device via g_sel_done).
    cudaStreamWaitEvent(0, evSel, 0);
}

// round 15
// speedup vs baseline: 2.8335x; 1.3788x over previous
#include <cuda_runtime.h>
#include <cuda_fp16.h>
#include <mma.h>
#include <cstdint>

using namespace nvcuda;

// ---------------- problem constants ----------------
#define BATCH      4
#define N1_PER     16384
#define N2_PER     4096
#define N1_TOT     (BATCH * N1_PER)    // 65536
#define N2_TOT     (BATCH * N2_PER)    // 16384
#define C_IN       512
#define C_OUT      256
#define BN_EPS     1e-5f

// ---------------- device scratch (static, allocation-free) ----------------
__device__ float g_h2[N2_TOT * C_OUT];                    // 16 MB
__device__ __half g_x1f[N1_TOT * C_OUT];
__device__ __half g_x2f[N2_TOT * C_IN];
__device__ __half g_W1f[C_OUT * C_OUT];
__device__ __half g_W2f[C_OUT * C_IN];
__device__ float g_c1[C_OUT];
__device__ float g_c2[C_OUT];
// kNN scratch (SoA)
__device__ int   g_ki0[N1_TOT], g_ki1[N1_TOT], g_ki2[N1_TOT];
__device__ float g_kw0[N1_TOT], g_kw1[N1_TOT], g_kw2[N1_TOT];
// device-side join flags (zeroed every launch/replay)
__device__ int g_h2_done;
__device__ int g_sel_done;

__global__ void zero_flags_kernel() { g_h2_done = 0; g_sel_done = 0; }

// ---------------- cp.async helpers ----------------
__device__ __forceinline__ void cp_async16(uint32_t smem, const void* gptr) {
    asm volatile("cp.async.cg.shared.global [%0], [%1], 16;" :: "r"(smem), "l"(gptr));
}
__device__ __forceinline__ void cp_commit() {
    asm volatile("cp.async.commit_group;");
}
__device__ __forceinline__ void cp_wait0() {
    asm volatile("cp.async.wait_group 0;");
}

// -------- BN fold + fp16 convert of BOTH weight matrices (one launch) -----
__global__ void fold_convert_Wboth(
    const float* __restrict__ W1, const float* __restrict__ b1,
    const float* __restrict__ g1, const float* __restrict__ be1,
    const float* __restrict__ m1, const float* __restrict__ v1,
    const float* __restrict__ W2, const float* __restrict__ b2,
    const float* __restrict__ g2, const float* __restrict__ be2,
    const float* __restrict__ m2, const float* __restrict__ v2)
{
    const int which = (blockIdx.x >= 256);
    const int n = blockIdx.x & 255;
    const int Kd = which ? C_IN : C_OUT;
    const float* W  = which ? W2 : W1;
    const float* b  = which ? b2 : b1;
    const float* g  = which ? g2 : g1;
    const float* be = which ? be2 : be1;
    const float* m  = which ? m2 : m1;
    const float* v  = which ? v2 : v1;
    __half* Wf = which ? g_W2f : g_W1f;
    float* cf = which ? g_c2 : g_c1;

    float s = g[n] / sqrtf(v[n] + BN_EPS);
    if (threadIdx.x == 0) cf[n] = (b[n] - m[n]) * s + be[n];
    for (int k = threadIdx.x; k < Kd; k += blockDim.x)
        Wf[n * Kd + k] = __float2half_rn(W[n * Kd + k] * s);
}

// -------- fp16 convert of activations (4 elements / thread) ----------------
__global__ void convert_x(const float* __restrict__ x,
                          __half* __restrict__ xf, int n)
{
    int i = (blockIdx.x * blockDim.x + threadIdx.x) * 4;
    if (i >= n) return;
    float4 v = *(const float4*)(x + i);
    __half2 h01 = __floats2half2_rn(v.x, v.y);
    __half2 h23 = __floats2half2_rn(v.z, v.w);
    uint2 packed;
    packed.x = *(uint32_t*)&h01;
    packed.y = *(uint32_t*)&h23;
    *(uint2*)(xf + i) = packed;
}

// -------- tensor-core GEMM: single-pass fp16, fp32 accumulate --------------
// (R8/R13 proven structure) Block 128x128, 4 warps, 64x64 warp tiles,
// cp.async double-buffered K-32 steps, 2 tiles (A, B) per step.
// WHICH==1: h2 = relu(bn(x2@W2^T)) -> g_h2
// WHICH==0: out = relu(bn(x1@W1^T)) + kNN-interp (device-flag join)
#define LDS_AB 40
#define LDS_C  132
#define TILE_ELEMS (128 * LDS_AB)

template <int WHICH>
__device__ __forceinline__ void gemm_body(const int bn, const int bm, float* __restrict__ Cout)
{
    constexpr int K = (WHICH == 0) ? C_OUT : C_IN;
    constexpr int NSTEP = K / 32;

    const __half* __restrict__ A = (WHICH == 0) ? g_x1f : g_x2f;
    const __half* __restrict__ B = (WHICH == 0) ? g_W1f : g_W2f;
    const float* __restrict__ cb = (WHICH == 0) ? g_c1 : g_c2;
    float* __restrict__ Cp = (WHICH == 0) ? Cout : g_h2;

    extern __shared__ __align__(16) char smem_raw[];
    __half* tiles = (__half*)smem_raw;     // [2][2][TILE_ELEMS] : A, B
    float* Cs = (float*)smem_raw;          // [128][132] (epilogue)

    const int tid = threadIdx.x;
    const int wid = tid >> 5;
    const int warp_m = wid >> 1;
    const int warp_n = wid & 1;

    wmma::fragment<wmma::accumulator, 16, 16, 16, float> acc[4][4];
#pragma unroll
    for (int i = 0; i < 4; i++)
#pragma unroll
        for (int j = 0; j < 4; j++) wmma::fill_fragment(acc[i][j], 0.0f);

    const uint32_t smem_base = (uint32_t)__cvta_generic_to_shared(tiles);

    // per k-step: 2 tiles x 128 rows x 32 halfs = 1024 16B-chunks; 8/thread
    auto load_tiles = [&](int s, int buf) {
        const int kk = s * 32;
        const uint32_t bufoff = (uint32_t)buf * 2 * TILE_ELEMS * 2;  // bytes
#pragma unroll
        for (int j = 0; j < 8; j++) {
            int idx = tid + j * 128;                 // 0..1023
            int t   = idx >> 9;                      // 0..1
            int w   = idx & 511;
            int r   = w >> 2;
            int c   = (w & 3) * 8;
            const __half* src;
            if (t == 0) src = A + (size_t)(bm + r) * K + kk + c;
            else        src = B + (size_t)(bn + r) * K + kk + c;
            uint32_t dst = smem_base + bufoff +
                           (uint32_t)(t * TILE_ELEMS + r * LDS_AB + c) * 2;
            cp_async16(dst, src);
        }
        cp_commit();
    };

    load_tiles(0, 0);

    for (int s = 0; s < NSTEP; s++) {
        const int buf = s & 1;
        cp_wait0();
        __syncthreads();
        if (s + 1 < NSTEP) load_tiles(s + 1, buf ^ 1);

        const __half* tA = tiles + (size_t)buf * 2 * TILE_ELEMS;
        const __half* tB = tA + TILE_ELEMS;

#pragma unroll
        for (int kf = 0; kf < 2; kf++) {
            wmma::fragment<wmma::matrix_a, 16, 16, 16, __half, wmma::row_major> af[4];
            wmma::fragment<wmma::matrix_b, 16, 16, 16, __half, wmma::col_major> bf[4];
#pragma unroll
            for (int i = 0; i < 4; i++)
                wmma::load_matrix_sync(af[i], tA + (warp_m * 64 + i * 16) * LDS_AB + kf * 16, LDS_AB);
#pragma unroll
            for (int j = 0; j < 4; j++)
                wmma::load_matrix_sync(bf[j], tB + (warp_n * 64 + j * 16) * LDS_AB + kf * 16, LDS_AB);
#pragma unroll
            for (int i = 0; i < 4; i++)
#pragma unroll
                for (int j = 0; j < 4; j++)
                    wmma::mma_sync(acc[i][j], af[i], bf[j], acc[i][j]);
        }
        __syncthreads();
    }

#pragma unroll
    for (int i = 0; i < 4; i++)
#pragma unroll
        for (int j = 0; j < 4; j++)
            wmma::store_matrix_sync(Cs + (warp_m * 64 + i * 16) * LDS_C + warp_n * 64 + j * 16,
                                    acc[i][j], LDS_C, wmma::mem_row_major);
    __syncthreads();

    if constexpr (WHICH == 0) {
        // device-side join: wait for h2 (256 CTAs) + select (256 CTAs)
        if (tid == 0) {
            volatile int* ph = &g_h2_done;
            volatile int* ps = &g_sel_done;
            while (*ph < 256 || *ps < 256) __nanosleep(128);
            __threadfence();
        }
        __syncthreads();

        // fused epilogue: relu(gemm+bias) + kNN-weighted h2 rows -> out
        const unsigned full = 0xffffffffu;
        const int warp = tid >> 5, lane = tid & 31;
        const int scene = bm / N1_PER;
        const int h2base = scene * N2_PER;
        const int q = bm + tid;
        const int i0 = g_ki0[q], i1 = g_ki1[q], i2 = g_ki2[q];
        const float w0 = g_kw0[q], w1 = g_kw1[q], w2 = g_kw2[q];
        const float4 bv = *(const float4*)(cb + bn + lane * 4);

        for (int s = 0; s < 32; s++) {
            float ww0 = __shfl_sync(full, w0, s);
            float ww1 = __shfl_sync(full, w1, s);
            float ww2 = __shfl_sync(full, w2, s);
            int   j0  = __shfl_sync(full, i0, s);
            int   j1  = __shfl_sync(full, i1, s);
            int   j2  = __shfl_sync(full, i2, s);
            const int row = warp * 32 + s;
            const float4 a = ((const float4*)(g_h2 + (size_t)(h2base + j0) * 256 + bn))[lane];
            const float4 b = ((const float4*)(g_h2 + (size_t)(h2base + j1) * 256 + bn))[lane];
            const float4 c = ((const float4*)(g_h2 + (size_t)(h2base + j2) * 256 + bn))[lane];
            const float4 cs4 = *(const float4*)(Cs + row * LDS_C + lane * 4);
            float4 v;
            v.x = fmaxf(cs4.x + bv.x, 0.f) + ww0 * a.x + ww1 * b.x + ww2 * c.x;
            v.y = fmaxf(cs4.y + bv.y, 0.f) + ww0 * a.y + ww1 * b.y + ww2 * c.y;
            v.z = fmaxf(cs4.z + bv.z, 0.f) + ww0 * a.z + ww1 * b.z + ww2 * c.z;
            v.w = fmaxf(cs4.w + bv.w, 0.f) + ww0 * a.w + ww1 * b.w + ww2 * c.w;
            *(float4*)(Cp + (size_t)(bm + row) * 256 + bn + lane * 4) = v;
        }
    } else {
        const int r = tid;
        const float* csrow = Cs + r * LDS_C;
        float* orow = Cp + (size_t)(bm + r) * 256 + bn;
#pragma unroll
        for (int t = 0; t < 32; t++) {
            float4 v = *(const float4*)(csrow + t * 4);
            float4 bv = *(const float4*)(cb + bn + t * 4);
            v.x = fmaxf(v.x + bv.x, 0.f);
            v.y = fmaxf(v.y + bv.y, 0.f);
            v.z = fmaxf(v.z + bv.z, 0.f);
            v.w = fmaxf(v.w + bv.w, 0.f);
            *(float4*)(orow + t * 4) = v;
        }
    }
}

// Merged launch: bids 0..255 = gemm<1> (h2), bids 256..1279 = gemm<0> (out).
__global__ __launch_bounds__(128) void gemm_merged(float* __restrict__ out)
{
    const int bid = blockIdx.x;
    if (bid < 256) {
        gemm_body<1>((bid & 1) * 128, (bid >> 1) * 128, out);
        __syncthreads();
        if (threadIdx.x == 0) {
            __threadfence();
            atomicAdd(&g_h2_done, 1);
        }
    } else {
        const int b = bid - 256;
        gemm_body<0>((b & 1) * 128, (b >> 1) * 128, out);
    }
}

#define GEMM_SMEM (2 * 2 * TILE_ELEMS * 2 > 128 * LDS_C * 4 ? 2 * 2 * TILE_ELEMS * 2 : 128 * LDS_C * 4)

// ---------------- kNN select: split-scan (2 threads / query) ---------------
#define TOP3_UPD(s, kk, A0, A1, A2, I0, I1, I2)            \
    if (s < A2) {                                          \
        if (s < A1) {                                      \
            A2 = A1; I2 = I1;                              \
            if (s < A0) { A1 = A0; I1 = I0; A0 = s; I0 = kk; } \
            else        { A1 = s;  I1 = kk; }              \
        } else { A2 = s; I2 = kk; }                        \
    }

#define SEL_SMEM (N2_PER * 16 + 256 * 3 * 4 * 2)

__global__ __launch_bounds__(512) void knn_select_kernel(
    const float* __restrict__ p1, const float* __restrict__ p2)
{
    extern __shared__ __align__(16) char sm[];
    float4* pts = (float4*)sm;                       // [4096]
    float*  mb  = (float*)(sm + N2_PER * 16);        // [3][256]
    int*    mi  = (int*)(sm + N2_PER * 16 + 3072);   // [3][256]

    const int scene = blockIdx.y;
    const int tid   = threadIdx.x;
    const int qloc  = tid & 255;
    const int half  = tid >> 8;

    const float* p2s = p2 + (size_t)scene * N2_PER * 3;
    for (int i = tid; i < N2_PER; i += 512) {
        pts[i] = make_float4(p2s[3 * i + 0], p2s[3 * i + 1], p2s[3 * i + 2], 0.f);
    }
    __syncthreads();

    const int q = scene * N1_PER + blockIdx.x * 256 + qloc;
    const float qx = p1[3 * q + 0];
    const float qy = p1[3 * q + 1];
    const float qz = p1[3 * q + 2];

    float b0 = 3.4e38f, b1 = 3.4e38f, b2 = 3.4e38f;
    int   i0 = 0, i1 = 0, i2 = 0;

    const int kbeg = half * (N2_PER / 2);
    const int kend = kbeg + (N2_PER / 2);
#pragma unroll 2
    for (int k = kbeg; k < kend; k += 4) {
        float4 pa = pts[k + 0];
        float4 pb = pts[k + 1];
        float4 pc = pts[k + 2];
        float4 pd = pts[k + 3];
        float dxa = qx - pa.x, dya = qy - pa.y, dza = qz - pa.z;
        float da  = fmaf(dxa, dxa, fmaf(dya, dya, dza * dza));
        float dxb = qx - pb.x, dyb = qy - pb.y, dzb = qz - pb.z;
        float db  = fmaf(dxb, dxb, fmaf(dyb, dyb, dzb * dzb));
        float dxc = qx - pc.x, dyc = qy - pc.y, dzc = qz - pc.z;
        float dc  = fmaf(dxc, dxc, fmaf(dyc, dyc, dzc * dzc));
        float dxd = qx - pd.x, dyd = qy - pd.y, dzd = qz - pd.z;
        float dd  = fmaf(dxd, dxd, fmaf(dyd, dyd, dzd * dzd));
        float m = fminf(fminf(da, db), fminf(dc, dd));
        if (m < b2) {
            TOP3_UPD(da, k + 0, b0, b1, b2, i0, i1, i2);
            TOP3_UPD(db, k + 1, b0, b1, b2, i0, i1, i2);
            TOP3_UPD(dc, k + 2, b0, b1, b2, i0, i1, i2);
            TOP3_UPD(dd, k + 3, b0, b1, b2, i0, i1, i2);
        }
    }

    if (half == 1) {
        mb[0 * 256 + qloc] = b0; mi[0 * 256 + qloc] = i0;
        mb[1 * 256 + qloc] = b1; mi[1 * 256 + qloc] = i1;
        mb[2 * 256 + qloc] = b2; mi[2 * 256 + qloc] = i2;
    }
    __syncthreads();

    if (half == 0) {
#pragma unroll
        for (int t = 0; t < 3; t++) {
            float d = mb[t * 256 + qloc];
            int   ii = mi[t * 256 + qloc];
            TOP3_UPD(d, ii, b0, b1, b2, i0, i1, i2);
        }

        float w0 = 1.f / (sqrtf(fmaxf(b0, 1e-12f)) + 1e-8f);
        float w1 = 1.f / (sqrtf(fmaxf(b1, 1e-12f)) + 1e-8f);
        float w2 = 1.f / (sqrtf(fmaxf(b2, 1e-12f)) + 1e-8f);
        float ws = w0 + w1 + w2;

        g_ki0[q] = i0; g_ki1[q] = i1; g_ki2[q] = i2;
        g_kw0[q] = w0 / ws; g_kw1[q] = w1 / ws; g_kw2[q] = w2 / ws;
    }

    __syncthreads();
    if (tid == 0) {
        __threadfence();
        atomicAdd(&g_sel_done, 1);
    }
}

// ---------------- launch -----------------
extern "C" void kernel_launch(void* const* d_in, const int* in_sizes, int n_in,
                              void* d_out, int out_size)
{
    const float* p1  = (const float*)d_in[0];
    const float* x1  = (const float*)d_in[1];
    const float* p2  = (const float*)d_in[2];
    const float* x2  = (const float*)d_in[3];
    const float* W1  = (const float*)d_in[4];
    const float* b1  = (const float*)d_in[5];
    const float* g1  = (const float*)d_in[6];
    const float* be1 = (const float*)d_in[7];
    const float* m1  = (const float*)d_in[8];
    const float* v1  = (const float*)d_in[9];
    const float* W2  = (const float*)d_in[10];
    const float* b2  = (const float*)d_in[11];
    const float* g2  = (const float*)d_in[12];
    const float* be2 = (const float*)d_in[13];
    const float* m2  = (const float*)d_in[14];
    const float* v2  = (const float*)d_in[15];
    float* out = (float*)d_out;

    static bool init_done = false;
    static cudaStream_t s2 = nullptr, s3 = nullptr;
    static cudaEvent_t evFork = nullptr, evSel = nullptr, evCx1 = nullptr;
    if (!init_done) {
        cudaFuncSetAttribute(gemm_merged, cudaFuncAttributeMaxDynamicSharedMemorySize, GEMM_SMEM);
        cudaFuncSetAttribute(knn_select_kernel, cudaFuncAttributeMaxDynamicSharedMemorySize,
                             SEL_SMEM);
        cudaStreamCreateWithFlags(&s2, cudaStreamNonBlocking);
        cudaStreamCreateWithFlags(&s3, cudaStreamNonBlocking);
        cudaEventCreateWithFlags(&evFork, cudaEventDisableTiming);
        cudaEventCreateWithFlags(&evSel, cudaEventDisableTiming);
        cudaEventCreateWithFlags(&evCx1, cudaEventDisableTiming);
        init_done = true;
    }

    __half *x1f, *x2f;
    cudaGetSymbolAddress((void**)&x1f, g_x1f);
    cudaGetSymbolAddress((void**)&x2f, g_x2f);

    // ---- zero flags, then fork ----
    zero_flags_kernel<<<1, 1>>>();
    cudaEventRecord(evFork, 0);
    cudaStreamWaitEvent(s2, evFork, 0);
    cudaStreamWaitEvent(s3, evFork, 0);

    // s2: kNN selection (signals g_sel_done via device flag)
    {
        dim3 gridk(N1_PER / 256, BATCH);
        knn_select_kernel<<<gridk, 512, SEL_SMEM, s2>>>(p1, p2);
    }
    cudaEventRecord(evSel, s2);

    // s3: convert x1 (needed by gemm<0> mainloop)
    {
        int n1 = N1_TOT * C_OUT;
        convert_x<<<n1 / 4 / 256, 256, 0, s3>>>(x1, x1f, n1);
    }
    cudaEventRecord(evCx1, s3);

    // ---- main stream: fused folds + convert_x2 ----
    fold_convert_Wboth<<<512, 128>>>(W1, b1, g1, be1, m1, v1,
                                     W2, b2, g2, be2, m2, v2);
    {
        int n2 = N2_TOT * C_IN;
        convert_x<<<n2 / 4 / 256, 256>>>(x2, x2f, n2);
    }

    // merged GEMM (x1 conversion via event; h2+select via device flags)
    cudaStreamWaitEvent(0, evCx1, 0);
    gemm_merged<<<1280, 128, GEMM_SMEM>>>(out);

    // join s2 into origin stream AFTER gemm launch (closes capture graph
    // without serializing gemm behind select).
    cudaStreamWaitEvent(0, evSel, 0);
}